// round 1
// baseline (speedup 1.0000x reference)
#include <cuda_runtime.h>

// ---------------------------------------------------------------------------
// TransformerXL relative position embedding, GB300 sm_103a
//
// out[b,n,u,w,c] = sum_h Q[b,u,w,n,h]*K[b,u,c,n,h]
//                + (0 <= c-w < 128 ? sum_h Q[b,u,w,n,h]*E[c-w,n,h] : 0)
// with E[f,n,h] = sum_d sig(f,d) * pos_kernel[d,n,h],
//      sig(f,d) = sin((127-f)*invts[d])      d < 256
//               = cos((127-f)*invts[d-256])  d >= 256
//      invts[j] = exp(-j * ln(10000)/255)
// ---------------------------------------------------------------------------

namespace {
constexpr int Bb = 4, Uu = 32, Ww = 128, Nn = 8, Hh = 64;
constexpr int Cc = 255, Ff = 128;
constexpr int QS = 132;                  // sQt row stride (floats); 528B rows, 16B aligned
constexpr int KS = 261;                  // sKE row stride (floats); gcd(261,32)=1 -> conflict-free transpose stores
constexpr int SMEM_FLOATS = 64 * QS + 64 * KS + 128 * 128;
constexpr int SMEM_BYTES = SMEM_FLOATS * 4;  // 166,144 B
}

// E scratch: [n][h][f]  (8*64*128 floats = 256 KB)
__device__ float g_E[Nn * Hh * Ff];

// ---------------------------------------------------------------------------
// f32x2 helpers (sm_103a packed fp32 FMA — 2x FFMA throughput, PTX-only)
// ---------------------------------------------------------------------------
__device__ __forceinline__ unsigned long long pack2(float v) {
    unsigned long long r;
    asm("mov.b64 %0, {%1, %1};" : "=l"(r) : "f"(v));
    return r;
}
__device__ __forceinline__ void fma2(unsigned long long& d,
                                     unsigned long long a,
                                     unsigned long long b) {
    asm("fma.rn.f32x2 %0, %1, %2, %0;" : "+l"(d) : "l"(a), "l"(b));
}
__device__ __forceinline__ float2 unpack2(unsigned long long v) {
    float2 r;
    asm("mov.b64 {%0, %1}, %2;" : "=f"(r.x), "=f"(r.y) : "l"(v));
    return r;
}

// ---------------------------------------------------------------------------
// Kernel A: E[n][h][f] = sum_d sig(f,d) * pos_kernel[d][n][h]
// grid 32 blocks x 4 f-values, 256 threads. ~33 MFLOP total.
// ---------------------------------------------------------------------------
__global__ void compute_E_kernel(const float* __restrict__ pk) {
    __shared__ float sig[4][512];
    const int f0 = blockIdx.x * 4;
    const float log_inc = 9.210340371976184f / 255.0f;  // ln(10000)/255

    for (int t = threadIdx.x; t < 4 * 512; t += 256) {
        int ff = t >> 9;
        int d  = t & 511;
        int j  = d & 255;
        float inv = expf(-(float)j * log_inc);
        float arg = (float)(127 - (f0 + ff)) * inv;
        sig[ff][d] = (d < 256) ? sinf(arg) : cosf(arg);
    }
    __syncthreads();

    for (int idx = threadIdx.x; idx < 512; idx += 256) {   // idx = n*64+h
        float a0 = 0.f, a1 = 0.f, a2 = 0.f, a3 = 0.f;
        #pragma unroll 8
        for (int d = 0; d < 512; ++d) {
            float v = pk[d * 512 + idx];
            a0 = fmaf(sig[0][d], v, a0);
            a1 = fmaf(sig[1][d], v, a1);
            a2 = fmaf(sig[2][d], v, a2);
            a3 = fmaf(sig[3][d], v, a3);
        }
        float* dst = &g_E[idx * Ff + f0];
        dst[0] = a0; dst[1] = a1; dst[2] = a2; dst[3] = a3;
    }
}

// ---------------------------------------------------------------------------
// Kernel B: one CTA per (b,u,n). 512 threads.
//   phase 1: BD = Q @ E_n^T (128x128) -> smem
//   phase 2: AC = Q @ K^T (128x255), epilogue adds shifted BD, writes out.
// Microtile: 8 rows (as 4 f32x2 row-pairs) x 8 cols (strided by 32 -> coalesced).
// ---------------------------------------------------------------------------
__global__ __launch_bounds__(512, 1)
void txl_main_kernel(const float* __restrict__ q_g,
                     const float* __restrict__ k_g,
                     float* __restrict__ out_g) {
    extern __shared__ float smem[];
    float* sQt = smem;                    // [64][QS]  Q^T : sQt[k*QS + w]
    float* sKE = smem + 64 * QS;          // [64][KS]  E^T then K^T : sKE[k*KS + c]
    float* sBD = sKE + 64 * KS;           // [128][128] BD tile

    const int tid = threadIdx.x;
    const int tx  = tid & 31;             // 0..31 (column lane)
    const int ty  = tid >> 5;             // 0..15 (row group)

    const int bid = blockIdx.x;
    const int n = bid & 7;
    const int u = (bid >> 3) & 31;
    const int b = bid >> 8;

    const float* Q = q_g + (size_t)(b * Uu + u) * Ww * (Nn * Hh) + n * Hh;
    const float* K = k_g + (size_t)(b * Uu + u) * Cc * (Nn * Hh) + n * Hh;
    const float* E = g_E + n * (Hh * Ff);
    float* OUT = out_g + (size_t)((b * Nn + n) * Uu + u) * Ww * Cc;

    // ---- load Q^T (transpose) and E^T (already [h][f]) ----
    for (int i = tid; i < Ww * Hh; i += 512) {
        int w = i >> 6, h = i & 63;
        sQt[h * QS + w] = Q[(size_t)w * 512 + h];
    }
    for (int i = tid; i < Hh * Ff; i += 512) {
        int h = i >> 7, f = i & 127;
        sKE[h * KS + f] = E[i];
    }
    __syncthreads();

    // ---- phase 1: BD(128x128) = Q @ E^T ----
    {
        unsigned long long accb[4][4];    // [col jj][row-pair p]
        #pragma unroll
        for (int a = 0; a < 4; ++a)
            #pragma unroll
            for (int p = 0; p < 4; ++p) accb[a][p] = 0ull;

        #pragma unroll 4
        for (int k = 0; k < 64; ++k) {
            const ulonglong2* qp =
                reinterpret_cast<const ulonglong2*>(&sQt[k * QS + ty * 8]);
            ulonglong2 qa = qp[0];        // row pairs (0,1),(2,3)
            ulonglong2 qb = qp[1];        // row pairs (4,5),(6,7)
            #pragma unroll
            for (int jj = 0; jj < 4; ++jj) {
                unsigned long long kk = pack2(sKE[k * KS + tx + 32 * jj]);
                fma2(accb[jj][0], qa.x, kk);
                fma2(accb[jj][1], qa.y, kk);
                fma2(accb[jj][2], qb.x, kk);
                fma2(accb[jj][3], qb.y, kk);
            }
        }
        #pragma unroll
        for (int jj = 0; jj < 4; ++jj) {
            int f = tx + 32 * jj;
            #pragma unroll
            for (int p = 0; p < 4; ++p) {
                float2 v = unpack2(accb[jj][p]);
                int w = ty * 8 + 2 * p;
                sBD[w * 128 + f]       = v.x;
                sBD[(w + 1) * 128 + f] = v.y;
            }
        }
    }
    __syncthreads();   // E reads done; BD stores visible

    // ---- load K^T (255 cols), zero pad col 255 ----
    for (int i = tid; i < Cc * Hh; i += 512) {
        int c = i >> 6, h = i & 63;
        sKE[h * KS + c] = K[(size_t)c * 512 + h];
    }
    if (tid < 64) sKE[tid * KS + 255] = 0.f;
    __syncthreads();

    // ---- phase 2: AC(128x256) = Q @ K^T, fused shifted-BD epilogue ----
    unsigned long long acc[8][4];         // [col j][row-pair p]
    #pragma unroll
    for (int a = 0; a < 8; ++a)
        #pragma unroll
        for (int p = 0; p < 4; ++p) acc[a][p] = 0ull;

    #pragma unroll 2
    for (int k = 0; k < 64; ++k) {
        const ulonglong2* qp =
            reinterpret_cast<const ulonglong2*>(&sQt[k * QS + ty * 8]);
        ulonglong2 qa = qp[0];
        ulonglong2 qb = qp[1];
        #pragma unroll
        for (int j = 0; j < 8; ++j) {
            unsigned long long kk = pack2(sKE[k * KS + tx + 32 * j]);
            fma2(acc[j][0], qa.x, kk);
            fma2(acc[j][1], qa.y, kk);
            fma2(acc[j][2], qb.x, kk);
            fma2(acc[j][3], qb.y, kk);
        }
    }

    // epilogue: out[w,c] = AC + (0 <= c-w < 128 ? BD[w, c-w] : 0)
    #pragma unroll
    for (int j = 0; j < 8; ++j) {
        int c = tx + 32 * j;
        if (c >= Cc) continue;            // skip pad column 255
        #pragma unroll
        for (int p = 0; p < 4; ++p) {
            int w0 = ty * 8 + 2 * p;
            float2 v = unpack2(acc[j][p]);
            int f0 = c - w0;
            if (f0 >= 0 && f0 < Ff) v.x += sBD[w0 * 128 + f0];
            int f1 = c - w0 - 1;
            if (f1 >= 0 && f1 < Ff) v.y += sBD[(w0 + 1) * 128 + f1];
            OUT[(size_t)w0 * Cc + c]       = v.x;
            OUT[(size_t)(w0 + 1) * Cc + c] = v.y;
        }
    }
}

// ---------------------------------------------------------------------------
extern "C" void kernel_launch(void* const* d_in, const int* in_sizes, int n_in,
                              void* d_out, int out_size) {
    (void)in_sizes; (void)n_in; (void)out_size;
    const float* q  = (const float*)d_in[0];   // queries (4,32,128,8,64)
    const float* k  = (const float*)d_in[1];   // keys    (4,32,255,8,64)
    const float* pk = (const float*)d_in[2];   // pos_kernel (512,8,64)
    float* out = (float*)d_out;                // (4,8,32,128,255)

    compute_E_kernel<<<32, 256>>>(pk);

    cudaFuncSetAttribute(txl_main_kernel,
                         cudaFuncAttributeMaxDynamicSharedMemorySize, SMEM_BYTES);
    txl_main_kernel<<<Bb * Uu * Nn, 512, SMEM_BYTES>>>(q, k, out);
}

// round 3
// speedup vs baseline: 1.5134x; 1.5134x over previous
#include <cuda_runtime.h>
#include <cstdint>

// ---------------------------------------------------------------------------
// TransformerXL relative position embedding — mma.sync tf32 (3x split)
//
// out[b,n,u,w,c] = AC[w,c] + (0 <= c-w < 128 ? BD[w, c-w] : 0)
//   AC = Q(128x64) @ K(255x64)^T   (per b,u,n)
//   BD = Q(128x64) @ E_n(128x64)^T
//   E[f,n,h] = sum_d sig(f,d) * pos_kernel[d,n,h]
// ---------------------------------------------------------------------------

namespace {
constexpr int Uu = 32, Nn = 8, Cc = 255;
constexpr int SQ  = 72;                 // smem tile row stride (floats)
constexpr int OFF_QH = 0;               // Q hi   128 x SQ
constexpr int OFF_QL = 9216;            // Q lo
constexpr int OFF_BH = 18432;           // B hi (E or K half), 128 x SQ
constexpr int OFF_BL = 27648;           // B lo
constexpr int OFF_BD = 36864;           // BD staging 128 x BDS
constexpr int BDS = 132;
constexpr int SMEM_BYTES = (OFF_BD + 128 * BDS) * 4;   // 215,040 B
}

// E scratch: [n][f][h]  (8*128*64 floats = 256 KB)
__device__ float g_E[Nn * 128 * 64];

__device__ __forceinline__ float tf32r(float x) {
    float r;
    asm("cvt.rna.tf32.f32 %0, %1;" : "=f"(r) : "f"(x));
    return r;
}

// D += A*B, m16n8k8 tf32 (baseline PTX, legal at plain sm_103 target)
__device__ __forceinline__ void mma8(float* c, const float* a, const float* b) {
    asm volatile(
        "mma.sync.aligned.m16n8k8.row.col.f32.tf32.tf32.f32 "
        "{%0,%1,%2,%3}, {%4,%5,%6,%7}, {%8,%9}, {%0,%1,%2,%3};"
        : "+f"(c[0]), "+f"(c[1]), "+f"(c[2]), "+f"(c[3])
        : "r"(__float_as_uint(a[0])), "r"(__float_as_uint(a[1])),
          "r"(__float_as_uint(a[2])), "r"(__float_as_uint(a[3])),
          "r"(__float_as_uint(b[0])), "r"(__float_as_uint(b[1])));
}

// permuted column: within each 8-wide k block, k -> (k&3)*2 + (k>>2)
// so fragment elements (k=t, k=t+4) sit at adjacent columns (2t, 2t+1).
__device__ __forceinline__ int pcol(int h) {
    return (h & ~7) | ((h & 3) << 1) | ((h >> 2) & 1);
}

__device__ __forceinline__ void split4(float* __restrict__ hi,
                                       float* __restrict__ lo,
                                       int row, int h4, float4 v) {
    float vv[4] = {v.x, v.y, v.z, v.w};
    #pragma unroll
    for (int e = 0; e < 4; ++e) {
        int col = pcol(h4 + e);
        float a = tf32r(vv[e]);
        hi[row * SQ + col] = a;
        lo[row * SQ + col] = tf32r(vv[e] - a);
    }
}

// 3x-split 32x32 warp-tile GEMM over K=64: acc += Q(rows 32*wm..) * B(rows 32*wn..)^T
__device__ __forceinline__ void gemm_32x32(const float* __restrict__ sm,
                                           float acc[2][4][4],
                                           int wm, int wn, int g, int t) {
    #pragma unroll
    for (int kb = 0; kb < 8; ++kb) {
        const int cb = kb * 8 + 2 * t;
        float aH[2][4], aL[2][4];
        #pragma unroll
        for (int i = 0; i < 2; ++i) {
            const int r = 32 * wm + 16 * i + g;
            float2 x0 = *(const float2*)&sm[OFF_QH + r * SQ + cb];
            float2 x1 = *(const float2*)&sm[OFF_QH + (r + 8) * SQ + cb];
            aH[i][0] = x0.x; aH[i][1] = x1.x; aH[i][2] = x0.y; aH[i][3] = x1.y;
            float2 y0 = *(const float2*)&sm[OFF_QL + r * SQ + cb];
            float2 y1 = *(const float2*)&sm[OFF_QL + (r + 8) * SQ + cb];
            aL[i][0] = y0.x; aL[i][1] = y1.x; aL[i][2] = y0.y; aL[i][3] = y1.y;
        }
        #pragma unroll
        for (int j = 0; j < 4; ++j) {
            const int br = 32 * wn + 8 * j + g;
            float2 bh = *(const float2*)&sm[OFF_BH + br * SQ + cb];
            float2 bl = *(const float2*)&sm[OFF_BL + br * SQ + cb];
            float bH[2] = {bh.x, bh.y};
            float bL[2] = {bl.x, bl.y};
            #pragma unroll
            for (int i = 0; i < 2; ++i) {
                mma8(acc[i][j], aH[i], bH);   // qh*kh
                mma8(acc[i][j], aH[i], bL);   // qh*kl
                mma8(acc[i][j], aL[i], bH);   // ql*kh
            }
        }
    }
}

// ---------------------------------------------------------------------------
// Kernel A: E[n][f][h] = sum_d sig(f,d) * pk[d][n*64+h].  64 blocks x 512 thr.
// ---------------------------------------------------------------------------
__global__ void compute_E_kernel(const float* __restrict__ pk) {
    __shared__ float sig0[512], sig1[512];
    const int f0 = blockIdx.x * 2;
    const float log_inc = 9.210340371976184f / 255.0f;

    for (int tt = threadIdx.x; tt < 1024; tt += 512) {
        int ff = tt >> 9, d = tt & 511, j = d & 255;
        float inv = expf(-(float)j * log_inc);
        float arg = (float)(127 - (f0 + ff)) * inv;
        float s = (d < 256) ? sinf(arg) : cosf(arg);
        (ff ? sig1 : sig0)[d] = s;
    }
    __syncthreads();

    const int nh = threadIdx.x;
    float a0 = 0.f, a1 = 0.f;
    #pragma unroll 16
    for (int d = 0; d < 512; ++d) {
        float v = __ldg(&pk[d * 512 + nh]);
        a0 = fmaf(sig0[d], v, a0);
        a1 = fmaf(sig1[d], v, a1);
    }
    int n = nh >> 6, h = nh & 63;
    g_E[n * 8192 + f0 * 64 + h] = a0;
    g_E[n * 8192 + (f0 + 1) * 64 + h] = a1;
}

// ---------------------------------------------------------------------------
// Main kernel: one CTA per (b,u,n), 512 threads (16 warps as 4x4).
// ---------------------------------------------------------------------------
__global__ __launch_bounds__(512, 1)
void txl_mma_kernel(const float* __restrict__ q_g,
                    const float* __restrict__ k_g,
                    float* __restrict__ out_g) {
    extern __shared__ float sm[];

    const int tid = threadIdx.x;
    const int lane = tid & 31, wid = tid >> 5;
    const int wm = wid & 3, wn = wid >> 2;
    const int g = lane >> 2, t = lane & 3;

    const int bid = blockIdx.x;
    const int n = bid & 7, u = (bid >> 3) & 31, b = bid >> 8;

    const float* Q  = q_g + (size_t)(b * Uu + u) * 128 * 512 + n * 64;
    const float* Kg = k_g + (size_t)(b * Uu + u) * Cc * 512 + n * 64;
    const float* E  = g_E + n * 8192;
    float* OUT = out_g + (size_t)((b * Nn + n) * Uu + u) * 128 * Cc;

    // ---- load Q and E (hi/lo tf32 split, permuted layout) ----
    for (int idx = tid; idx < 2048; idx += 512) {
        int w = idx >> 4, h4 = (idx & 15) << 2;
        float4 v = *(const float4*)&Q[(size_t)w * 512 + h4];
        split4(sm + OFF_QH, sm + OFF_QL, w, h4, v);
        float4 e = *(const float4*)&E[w * 64 + h4];
        split4(sm + OFF_BH, sm + OFF_BL, w, h4, e);
    }
    __syncthreads();

    // ---- BD = Q @ E^T  (128x128), stage to smem ----
    {
        float acc[2][4][4] = {};
        gemm_32x32(sm, acc, wm, wn, g, t);
        #pragma unroll
        for (int i = 0; i < 2; ++i)
            #pragma unroll
            for (int j = 0; j < 4; ++j) {
                int w0 = 32 * wm + 16 * i + g;
                int f0 = 32 * wn + 8 * j + 2 * t;
                *(float2*)&sm[OFF_BD + w0 * BDS + f0] =
                    make_float2(acc[i][j][0], acc[i][j][1]);
                *(float2*)&sm[OFF_BD + (w0 + 8) * BDS + f0] =
                    make_float2(acc[i][j][2], acc[i][j][3]);
            }
    }
    __syncthreads();

    // ---- AC = Q @ K^T in two 128-col halves, fused shifted-BD epilogue ----
    #pragma unroll 1
    for (int half = 0; half < 2; ++half) {
        for (int idx = tid; idx < 2048; idx += 512) {
            int r = idx >> 4, c = 128 * half + r, h4 = (idx & 15) << 2;
            float4 v = (c < Cc) ? *(const float4*)&Kg[(size_t)c * 512 + h4]
                                : make_float4(0.f, 0.f, 0.f, 0.f);
            split4(sm + OFF_BH, sm + OFF_BL, r, h4, v);
        }
        __syncthreads();

        float acc[2][4][4] = {};
        gemm_32x32(sm, acc, wm, wn, g, t);

        #pragma unroll
        for (int i = 0; i < 2; ++i)
            #pragma unroll
            for (int j = 0; j < 4; ++j) {
                int c0 = 128 * half + 32 * wn + 8 * j + 2 * t;
                #pragma unroll
                for (int p = 0; p < 2; ++p) {
                    int w = 32 * wm + 16 * i + g + 8 * p;
                    float v0 = acc[i][j][2 * p];
                    float v1 = acc[i][j][2 * p + 1];
                    int f0 = c0 - w;
                    if (f0 >= 0 && f0 < 128)     v0 += sm[OFF_BD + w * BDS + f0];
                    if (f0 + 1 >= 0 && f0 + 1 < 128) v1 += sm[OFF_BD + w * BDS + f0 + 1];
                    if (c0 < Cc)     OUT[(size_t)w * Cc + c0]     = v0;
                    if (c0 + 1 < Cc) OUT[(size_t)w * Cc + c0 + 1] = v1;
                }
            }
        if (half == 0) __syncthreads();   // before overwriting K tiles
    }
}

// ---------------------------------------------------------------------------
extern "C" void kernel_launch(void* const* d_in, const int* in_sizes, int n_in,
                              void* d_out, int out_size) {
    (void)in_sizes; (void)n_in; (void)out_size;
    const float* q  = (const float*)d_in[0];   // queries (4,32,128,8,64)
    const float* k  = (const float*)d_in[1];   // keys    (4,32,255,8,64)
    const float* pk = (const float*)d_in[2];   // pos_kernel (512,8,64)
    float* out = (float*)d_out;                // (4,8,32,128,255)

    compute_E_kernel<<<64, 512>>>(pk);

    cudaFuncSetAttribute(txl_mma_kernel,
                         cudaFuncAttributeMaxDynamicSharedMemorySize, SMEM_BYTES);
    txl_mma_kernel<<<4 * Uu * Nn, 512, SMEM_BYTES>>>(q, k, out);
}

// round 4
// speedup vs baseline: 1.8903x; 1.2490x over previous
#include <cuda_runtime.h>
#include <cuda_bf16.h>
#include <cstdint>

// ---------------------------------------------------------------------------
// TransformerXL relative position embedding — bf16 3x-split mma.sync m16n8k16
//
// out[b,n,u,w,c] = AC[w,c] + (0 <= c-w < 128 ? BD[w, c-w] : 0)
//   AC = Q(128x64) @ K(255x64)^T   (per b,u,n)
//   BD = Q(128x64) @ E_n(128x64)^T
//   E[f,n,h] = sum_d sig(f,d) * pos_kernel[d,n,h]
// ---------------------------------------------------------------------------

namespace {
constexpr int Uu = 32, Nn = 8, Cc = 255;

// smem (32-bit words):
//   sA  @0      : 128 rows x 64 words  (Q,  hi/lo bf16 fused)     32 KB
//   sB  @8192   : 128 rows x 64 words  (E / K-half)               32 KB
//   sBD @16384  : 128 x 136 fp32                                  69.6 KB
//   sST @33792  : 128 x 136 fp32 (output staging)                 69.6 KB
constexpr int OFF_B  = 8192;
constexpr int OFF_BD = 16384;
constexpr int OFF_ST = 33792;
constexpr int SMEM_WORDS = OFF_ST + 128 * 136;   // 51200
constexpr int SMEM_BYTES = SMEM_WORDS * 4;       // 204800
}

// E partial sums: [dq][f][nh], 4*128*512 floats = 1 MB
__device__ float g_Ep[4 * 128 * 512];

// ---------------------------------------------------------------------------
__device__ __forceinline__ void mma16(float* c, const uint32_t* a, const uint32_t* b) {
    asm volatile(
        "mma.sync.aligned.m16n8k16.row.col.f32.bf16.bf16.f32 "
        "{%0,%1,%2,%3}, {%4,%5,%6,%7}, {%8,%9}, {%0,%1,%2,%3};"
        : "+f"(c[0]), "+f"(c[1]), "+f"(c[2]), "+f"(c[3])
        : "r"(a[0]), "r"(a[1]), "r"(a[2]), "r"(a[3]), "r"(b[0]), "r"(b[1]));
}

__device__ __forceinline__ uint32_t pack_bf2(float e0, float e1) {
    __nv_bfloat162 h = __floats2bfloat162_rn(e0, e1);  // .x = e0 (low half)
    return *reinterpret_cast<uint32_t*>(&h);
}

// store one k-pair (p = k/2) as fused hi/lo words into a fragment-ordered row.
// word layout per row: idx = kb*16 + 2*p' + s,  p' = ((p&3)<<1)|((p>>2)&1), s=hi/lo
__device__ __forceinline__ void pack_pair(uint32_t* __restrict__ rowp, int p,
                                          float e0, float e1) {
    int kb = p >> 3, pp = p & 7;
    int pprime = ((pp & 3) << 1) | (pp >> 2);
    int wi = kb * 16 + (pprime << 1);
    float h0 = __bfloat162float(__float2bfloat16(e0));
    float h1 = __bfloat162float(__float2bfloat16(e1));
    rowp[wi]     = pack_bf2(h0, h1);
    rowp[wi + 1] = pack_bf2(e0 - h0, e1 - h1);
}

__device__ __forceinline__ void pack4(uint32_t* __restrict__ rowp, int h4, float4 v) {
    pack_pair(rowp, (h4 >> 1),     v.x, v.y);
    pack_pair(rowp, (h4 >> 1) + 1, v.z, v.w);
}

// 32x16 warp-tile gemm over K=64, 3x bf16 split. acc[i][j][4]
__device__ __forceinline__ void gemm_warp(const uint32_t* __restrict__ sA,
                                          const uint32_t* __restrict__ sB,
                                          float acc[2][2][4],
                                          int rm, int cn, int g, int t) {
    #pragma unroll
    for (int kb = 0; kb < 4; ++kb) {
        const int ko = kb * 16 + 4 * t;
        uint32_t aH[2][4], aL[2][4];
        #pragma unroll
        for (int i = 0; i < 2; ++i) {
            const uint4 f0 = *(const uint4*)&sA[(rm + 16 * i + g) * 64 + ko];
            const uint4 f1 = *(const uint4*)&sA[(rm + 16 * i + g + 8) * 64 + ko];
            aH[i][0] = f0.x; aH[i][1] = f1.x; aH[i][2] = f0.z; aH[i][3] = f1.z;
            aL[i][0] = f0.y; aL[i][1] = f1.y; aL[i][2] = f0.w; aL[i][3] = f1.w;
        }
        #pragma unroll
        for (int j = 0; j < 2; ++j) {
            const uint4 fb = *(const uint4*)&sB[(cn + 8 * j + g) * 64 + ko];
            uint32_t bH[2] = {fb.x, fb.z};
            uint32_t bL[2] = {fb.y, fb.w};
            #pragma unroll
            for (int i = 0; i < 2; ++i) {
                mma16(acc[i][j], aH[i], bH);
                mma16(acc[i][j], aH[i], bL);
                mma16(acc[i][j], aL[i], bH);
            }
        }
    }
}

// ---------------------------------------------------------------------------
// E partials: g_Ep[dq][f][nh] = sum_{d in quarter dq} sig(f,d)*pk[d][nh]
// grid 128 = 32 fgroups x 4 dq, block 512.
// ---------------------------------------------------------------------------
__global__ void compute_E_kernel(const float* __restrict__ pk) {
    __shared__ float sig[4][128];
    const int fg = blockIdx.x & 31, dq = blockIdx.x >> 5;
    const int f4 = fg * 4;
    const float log_inc = 9.210340371976184f / 255.0f;

    {
        int t = threadIdx.x;          // 512 threads fill 4x128
        int fi = t >> 7, dd = t & 127;
        int d = dq * 128 + dd, j = d & 255;
        float arg = (float)(127 - (f4 + fi)) * expf(-(float)j * log_inc);
        sig[fi][dd] = (d < 256) ? sinf(arg) : cosf(arg);
    }
    __syncthreads();

    const int nh = threadIdx.x;
    const float* p = pk + (size_t)(dq * 128) * 512 + nh;
    float a0 = 0.f, a1 = 0.f, a2 = 0.f, a3 = 0.f;
    #pragma unroll 8
    for (int dd = 0; dd < 128; ++dd) {
        float v = __ldg(&p[(size_t)dd * 512]);
        a0 = fmaf(sig[0][dd], v, a0);
        a1 = fmaf(sig[1][dd], v, a1);
        a2 = fmaf(sig[2][dd], v, a2);
        a3 = fmaf(sig[3][dd], v, a3);
    }
    float* o = g_Ep + dq * 65536 + f4 * 512 + nh;
    o[0] = a0; o[512] = a1; o[1024] = a2; o[1536] = a3;
}

// ---------------------------------------------------------------------------
// Main kernel: one CTA per (b,u,n), 1024 threads (32 warps as 4m x 8n).
// ---------------------------------------------------------------------------
__global__ __launch_bounds__(1024, 1)
void txl_mma_kernel(const float* __restrict__ q_g,
                    const float* __restrict__ k_g,
                    float* __restrict__ out_g) {
    extern __shared__ uint32_t sm[];
    uint32_t* sA = sm;
    uint32_t* sB = sm + OFF_B;
    float* sBD = reinterpret_cast<float*>(sm + OFF_BD);
    float* sST = reinterpret_cast<float*>(sm + OFF_ST);

    const int tid = threadIdx.x;
    const int lane = tid & 31, wid = tid >> 5;
    const int wm = wid & 3, wn = wid >> 2;          // 4 x 8 warp grid
    const int g = lane >> 2, t = lane & 3;

    const int bid = blockIdx.x;
    const int n = bid & 7, u = (bid >> 3) & 31, b = bid >> 8;

    const float* Q  = q_g + (size_t)(b * Uu + u) * 128 * 512 + n * 64;
    const float* Kg = k_g + (size_t)(b * Uu + u) * Cc * 512 + n * 64;
    float* OUT = out_g + (size_t)((b * Nn + n) * Uu + u) * 128 * Cc;

    // ---- pack Q -> sA, E (sum of 4 partials) -> sB ----
    for (int idx = tid; idx < 2048; idx += 1024) {
        const int row = idx >> 4, h4 = (idx & 15) << 2;
        float4 qv = *(const float4*)&Q[(size_t)row * 512 + h4];
        pack4(sA + row * 64, h4, qv);

        const float* ep = g_Ep + (size_t)row * 512 + n * 64 + h4;
        float4 e0 = *(const float4*)&ep[0];
        float4 e1 = *(const float4*)&ep[65536];
        float4 e2 = *(const float4*)&ep[131072];
        float4 e3 = *(const float4*)&ep[196608];
        e0.x += e1.x + e2.x + e3.x;  e0.y += e1.y + e2.y + e3.y;
        e0.z += e1.z + e2.z + e3.z;  e0.w += e1.w + e2.w + e3.w;
        pack4(sB + row * 64, h4, e0);
    }
    __syncthreads();

    // ---- BD = Q @ E^T -> sBD ----
    {
        float acc[2][2][4] = {};
        gemm_warp(sA, sB, acc, 32 * wm, 16 * wn, g, t);
        #pragma unroll
        for (int i = 0; i < 2; ++i)
            #pragma unroll
            for (int j = 0; j < 2; ++j) {
                const int w0 = 32 * wm + 16 * i + g;
                const int f0 = 16 * wn + 8 * j + 2 * t;
                *(float2*)&sBD[w0 * 136 + f0] =
                    make_float2(acc[i][j][0], acc[i][j][1]);
                *(float2*)&sBD[(w0 + 8) * 136 + f0] =
                    make_float2(acc[i][j][2], acc[i][j][3]);
            }
    }
    __syncthreads();

    // ---- AC halves ----
    #pragma unroll 1
    for (int half = 0; half < 2; ++half) {
        for (int idx = tid; idx < 2048; idx += 1024) {
            const int row = idx >> 4, h4 = (idx & 15) << 2;
            const int c = 128 * half + row;
            float4 kv = (c < Cc) ? *(const float4*)&Kg[(size_t)c * 512 + h4]
                                 : make_float4(0.f, 0.f, 0.f, 0.f);
            pack4(sB + row * 64, h4, kv);
        }
        __syncthreads();

        float acc[2][2][4] = {};
        gemm_warp(sA, sB, acc, 32 * wm, 16 * wn, g, t);

        // epilogue: add shifted BD, stage coalesced
        #pragma unroll
        for (int i = 0; i < 2; ++i)
            #pragma unroll
            for (int j = 0; j < 2; ++j) {
                const int lc = 16 * wn + 8 * j + 2 * t;     // local col 0..127
                const int c0 = 128 * half + lc;             // global col
                #pragma unroll
                for (int p = 0; p < 2; ++p) {
                    const int w = 32 * wm + 16 * i + g + 8 * p;
                    float v0 = acc[i][j][2 * p];
                    float v1 = acc[i][j][2 * p + 1];
                    const int f = c0 - w;
                    if (f >= 0 && f < 128)         v0 += sBD[w * 136 + f];
                    if (f + 1 >= 0 && f + 1 < 128) v1 += sBD[w * 136 + f + 1];
                    *(float2*)&sST[w * 136 + lc] = make_float2(v0, v1);
                }
            }
        __syncthreads();

        // coalesced copy stage -> OUT
        {
            const int row = tid >> 3, l8 = tid & 7;
            const float* src = &sST[row * 136];
            float* dst = &OUT[(size_t)row * Cc + 128 * half];
            #pragma unroll
            for (int i = 0; i < 16; ++i) {
                const int c = l8 + 8 * i;
                if (128 * half + c < Cc) dst[c] = src[c];
            }
        }
        __syncthreads();
    }
}

// ---------------------------------------------------------------------------
extern "C" void kernel_launch(void* const* d_in, const int* in_sizes, int n_in,
                              void* d_out, int out_size) {
    (void)in_sizes; (void)n_in; (void)out_size;
    const float* q  = (const float*)d_in[0];   // queries (4,32,128,8,64)
    const float* k  = (const float*)d_in[1];   // keys    (4,32,255,8,64)
    const float* pk = (const float*)d_in[2];   // pos_kernel (512,8,64)
    float* out = (float*)d_out;                // (4,8,32,128,255)

    compute_E_kernel<<<128, 512>>>(pk);

    cudaFuncSetAttribute(txl_mma_kernel,
                         cudaFuncAttributeMaxDynamicSharedMemorySize, SMEM_BYTES);
    txl_mma_kernel<<<4 * Uu * Nn, 1024, SMEM_BYTES>>>(q, k, out);
}

// round 5
// speedup vs baseline: 2.5078x; 1.3267x over previous
#include <cuda_runtime.h>
#include <cuda_fp16.h>
#include <cstdint>

// ---------------------------------------------------------------------------
// TransformerXL relative position embedding — fp16 3x-split mma.sync m16n8k16
//
// out[b,n,u,w,c] = AC[w,c] + (0 <= c-w < 128 ? BD[w, c-w] : 0)
//   AC = Q(128x64) @ K(255x64)^T   (per b,u,n)
//   BD = Q(128x64) @ E_n(128x64)^T
//   E[f,nh] = sum_d sig(f,d) * pos_kernel[d,nh]
// ---------------------------------------------------------------------------

namespace {
constexpr int Uu = 32, Nn = 8, Cc = 255;

constexpr int RS = 80;                  // tile row stride in 32-bit words (80%32==16 -> conflict-free)
constexpr int OFF_B0 = 128 * RS;        // 10240
constexpr int OFF_B1 = 2 * 128 * RS;    // 20480
constexpr int OFF_BD = 3 * 128 * RS;    // 30720 (floats from here)
constexpr int BDS = 136;
constexpr int SMEM_WORDS = OFF_BD + 128 * BDS;    // 48128
constexpr int SMEM_BYTES = SMEM_WORDS * 4;        // 192512
}

// E: [f][nh]  128*512 floats = 256 KB
__device__ float g_E[128 * 512];

// ---------------------------------------------------------------------------
__device__ __forceinline__ void mma16(float* c, const uint32_t* a, const uint32_t* b) {
    asm volatile(
        "mma.sync.aligned.m16n8k16.row.col.f32.f16.f16.f32 "
        "{%0,%1,%2,%3}, {%4,%5,%6,%7}, {%8,%9}, {%0,%1,%2,%3};"
        : "+f"(c[0]), "+f"(c[1]), "+f"(c[2]), "+f"(c[3])
        : "r"(a[0]), "r"(a[1]), "r"(a[2]), "r"(a[3]), "r"(b[0]), "r"(b[1]));
}

__device__ __forceinline__ uint32_t pack_h2(float a, float b) {
    __half2 h = __floats2half2_rn(a, b);
    return *reinterpret_cast<uint32_t*>(&h);
}

// store one k-pair (p = k/2) as fused hi/lo words, fragment-permuted.
__device__ __forceinline__ void pack_pair(uint32_t* __restrict__ rowp, int p,
                                          float e0, float e1) {
    int kb = p >> 3, pp = p & 7;
    int pprime = ((pp & 3) << 1) | (pp >> 2);
    int wi = kb * 16 + (pprime << 1);
    __half h0 = __float2half_rn(e0), h1 = __float2half_rn(e1);
    rowp[wi]     = pack_h2(__half2float(h0), __half2float(h1));
    rowp[wi + 1] = pack_h2(e0 - __half2float(h0), e1 - __half2float(h1));
}

__device__ __forceinline__ void pack4(uint32_t* __restrict__ rowp, int h4, float4 v) {
    pack_pair(rowp, (h4 >> 1),     v.x, v.y);
    pack_pair(rowp, (h4 >> 1) + 1, v.z, v.w);
}

// 32x32 warp-tile gemm over K=64, 3x fp16 split.
__device__ __forceinline__ void gemm_warp(const uint32_t* __restrict__ sA,
                                          const uint32_t* __restrict__ sB,
                                          float acc[2][4][4],
                                          int rm, int cn, int g, int t) {
    #pragma unroll
    for (int kb = 0; kb < 4; ++kb) {
        const int ko = kb * 16 + 4 * t;
        const uint4 x0 = *(const uint4*)&sA[(rm + g) * RS + ko];
        const uint4 x1 = *(const uint4*)&sA[(rm + g + 8) * RS + ko];
        const uint4 x2 = *(const uint4*)&sA[(rm + 16 + g) * RS + ko];
        const uint4 x3 = *(const uint4*)&sA[(rm + 24 + g) * RS + ko];
        uint32_t aH[2][4] = {{x0.x, x1.x, x0.z, x1.z}, {x2.x, x3.x, x2.z, x3.z}};
        uint32_t aL[2][4] = {{x0.y, x1.y, x0.w, x1.w}, {x2.y, x3.y, x2.w, x3.w}};
        #pragma unroll
        for (int j = 0; j < 4; ++j) {
            const uint4 fb = *(const uint4*)&sB[(cn + 8 * j + g) * RS + ko];
            uint32_t bH[2] = {fb.x, fb.z};
            uint32_t bL[2] = {fb.y, fb.w};
            #pragma unroll
            for (int i = 0; i < 2; ++i) {
                mma16(acc[i][j], aH[i], bH);
                mma16(acc[i][j], aH[i], bL);
                mma16(acc[i][j], aL[i], bH);
            }
        }
    }
}

// ---------------------------------------------------------------------------
// E kernel: grid 128 = (64 f-pairs) x (2 nh-halves), 1024 threads.
// thread = q(0..63: nh4 within half) x ch(0..15: 32-d chunk); smem reduce.
// ---------------------------------------------------------------------------
__global__ __launch_bounds__(1024)
void compute_E_kernel(const float* __restrict__ pk) {
    __shared__ float sig[2 * 512];
    __shared__ float sp[16 * 2 * 256];

    const int fg  = blockIdx.x & 63;
    const int nhh = blockIdx.x >> 6;
    const int f2  = fg * 2;
    const int nh0 = nhh * 256;
    const int tid = threadIdx.x;
    const float log_inc = 9.210340371976184f / 255.0f;

    {
        int fi = tid >> 9, d = tid & 511, j = d & 255;
        float arg = (float)(127 - (f2 + fi)) * expf(-(float)j * log_inc);
        sig[fi * 512 + d] = (d < 256) ? sinf(arg) : cosf(arg);
    }
    __syncthreads();

    const int q = tid & 63, ch = tid >> 6;
    const float* p = pk + (size_t)(ch * 32) * 512 + nh0 + 4 * q;
    float4 a0 = make_float4(0.f, 0.f, 0.f, 0.f);
    float4 a1 = make_float4(0.f, 0.f, 0.f, 0.f);
    #pragma unroll
    for (int dd = 0; dd < 32; ++dd) {
        float4 v = __ldg((const float4*)(p + (size_t)dd * 512));
        int d = ch * 32 + dd;
        float s0 = sig[d], s1 = sig[512 + d];
        a0.x = fmaf(s0, v.x, a0.x); a0.y = fmaf(s0, v.y, a0.y);
        a0.z = fmaf(s0, v.z, a0.z); a0.w = fmaf(s0, v.w, a0.w);
        a1.x = fmaf(s1, v.x, a1.x); a1.y = fmaf(s1, v.y, a1.y);
        a1.z = fmaf(s1, v.z, a1.z); a1.w = fmaf(s1, v.w, a1.w);
    }
    *(float4*)&sp[(ch * 2 + 0) * 256 + 4 * q] = a0;
    *(float4*)&sp[(ch * 2 + 1) * 256 + 4 * q] = a1;
    __syncthreads();

    if (tid < 128) {
        int fi = tid >> 6, qq = tid & 63;
        float4 s = make_float4(0.f, 0.f, 0.f, 0.f);
        #pragma unroll
        for (int c = 0; c < 16; ++c) {
            float4 v = *(const float4*)&sp[(c * 2 + fi) * 256 + 4 * qq];
            s.x += v.x; s.y += v.y; s.z += v.z; s.w += v.w;
        }
        *(float4*)&g_E[(f2 + fi) * 512 + nh0 + 4 * qq] = s;
    }
}

// ---------------------------------------------------------------------------
// Main kernel: one CTA per (b,u,n), 512 threads (16 warps, 4m x 4n).
// ---------------------------------------------------------------------------
__global__ __launch_bounds__(512, 1)
void txl_mma_kernel(const float* __restrict__ q_g,
                    const float* __restrict__ k_g,
                    float* __restrict__ out_g) {
    extern __shared__ uint32_t sm[];
    uint32_t* sA  = sm;
    uint32_t* sB0 = sm + OFF_B0;
    uint32_t* sB1 = sm + OFF_B1;
    float* sBD = reinterpret_cast<float*>(sm + OFF_BD);

    const int tid = threadIdx.x;
    const int lane = tid & 31, wid = tid >> 5;
    const int wm = wid & 3, wn = wid >> 2;
    const int g = lane >> 2, t = lane & 3;

    const int bid = blockIdx.x;
    const int n = bid & 7, u = (bid >> 3) & 31, b = bid >> 8;

    const float* Q  = q_g + (size_t)(b * Uu + u) * 128 * 512 + n * 64;
    const float* Kg = k_g + (size_t)(b * Uu + u) * Cc * 512 + n * 64;
    float* OUT = out_g + (size_t)((b * Nn + n) * Uu + u) * 128 * Cc;

    const int prow = tid >> 4;             // pack row for this thread (it=0)
    const int ph4  = (tid & 15) << 2;

    // ---- pack Q -> sA, E -> sB0; prefetch K0 -> regs ----
    float4 kreg[4];
    #pragma unroll
    for (int it = 0; it < 4; ++it) {
        const int row = prow + 32 * it;
        float4 qv = *(const float4*)&Q[(size_t)row * 512 + ph4];
        pack4(sA + row * RS, ph4, qv);
        float4 ev = *(const float4*)&g_E[row * 512 + n * 64 + ph4];
        pack4(sB0 + row * RS, ph4, ev);
        kreg[it] = *(const float4*)&Kg[(size_t)row * 512 + ph4];
    }
    __syncthreads();

    float acc[2][4][4];

    // ---- BD = Q @ E^T ----
    #pragma unroll
    for (int i = 0; i < 2; ++i)
        #pragma unroll
        for (int j = 0; j < 4; ++j)
            #pragma unroll
            for (int e = 0; e < 4; ++e) acc[i][j][e] = 0.f;
    gemm_warp(sA, sB0, acc, 32 * wm, 32 * wn, g, t);

    // pack K0 regs -> sB1; prefetch K1 -> regs
    #pragma unroll
    for (int it = 0; it < 4; ++it) {
        const int row = prow + 32 * it;
        pack4(sB1 + row * RS, ph4, kreg[it]);
        const int c = 128 + row;
        kreg[it] = (c < Cc) ? *(const float4*)&Kg[(size_t)c * 512 + ph4]
                            : make_float4(0.f, 0.f, 0.f, 0.f);
    }

    // stage BD to smem
    #pragma unroll
    for (int i = 0; i < 2; ++i)
        #pragma unroll
        for (int j = 0; j < 4; ++j) {
            const int w0 = 32 * wm + 16 * i + g;
            const int f0 = 32 * wn + 8 * j + 2 * t;
            *(float2*)&sBD[w0 * BDS + f0] = make_float2(acc[i][j][0], acc[i][j][1]);
            *(float2*)&sBD[(w0 + 8) * BDS + f0] = make_float2(acc[i][j][2], acc[i][j][3]);
        }
    __syncthreads();

    // ---- AC halves ----
    #pragma unroll 1
    for (int half = 0; half < 2; ++half) {
        const uint32_t* sB = half ? sB0 : sB1;

        #pragma unroll
        for (int i = 0; i < 2; ++i)
            #pragma unroll
            for (int j = 0; j < 4; ++j)
                #pragma unroll
                for (int e = 0; e < 4; ++e) acc[i][j][e] = 0.f;
        gemm_warp(sA, sB, acc, 32 * wm, 32 * wn, g, t);

        if (half == 0) {
            // pack K1 -> sB0 while nothing reads it
            #pragma unroll
            for (int it = 0; it < 4; ++it)
                pack4(sB0 + (prow + 32 * it) * RS, ph4, kreg[it]);
        }

        // epilogue: add shifted BD, direct scalar stores
        #pragma unroll
        for (int i = 0; i < 2; ++i)
            #pragma unroll
            for (int j = 0; j < 4; ++j) {
                const int c0 = 128 * half + 32 * wn + 8 * j + 2 * t;
                #pragma unroll
                for (int p = 0; p < 2; ++p) {
                    const int w = 32 * wm + 16 * i + g + 8 * p;
                    float v0 = acc[i][j][2 * p];
                    float v1 = acc[i][j][2 * p + 1];
                    const int f = c0 - w;
                    if (f >= 0 && f < 128)          v0 += sBD[w * BDS + f];
                    if (f + 1 >= 0 && f + 1 < 128)  v1 += sBD[w * BDS + f + 1];
                    float* o = &OUT[(size_t)w * Cc + c0];
                    o[0] = v0;
                    if (c0 + 1 < Cc) o[1] = v1;
                }
            }
        if (half == 0) __syncthreads();
    }
}

// ---------------------------------------------------------------------------
extern "C" void kernel_launch(void* const* d_in, const int* in_sizes, int n_in,
                              void* d_out, int out_size) {
    (void)in_sizes; (void)n_in; (void)out_size;
    const float* q  = (const float*)d_in[0];   // queries (4,32,128,8,64)
    const float* k  = (const float*)d_in[1];   // keys    (4,32,255,8,64)
    const float* pk = (const float*)d_in[2];   // pos_kernel (512,8,64)
    float* out = (float*)d_out;                // (4,8,32,128,255)

    compute_E_kernel<<<128, 1024>>>(pk);

    cudaFuncSetAttribute(txl_mma_kernel,
                         cudaFuncAttributeMaxDynamicSharedMemorySize, SMEM_BYTES);
    txl_mma_kernel<<<4 * Uu * Nn, 512, SMEM_BYTES>>>(q, k, out);
}

// round 6
// speedup vs baseline: 2.7292x; 1.0883x over previous
#include <cuda_runtime.h>
#include <cuda_fp16.h>
#include <cstdint>

// ---------------------------------------------------------------------------
// TransformerXL relative position embedding — fp16 3x-split mma.sync m16n8k16
// Split-M: one CTA per (b,u,n,mhalf), M=64 rows, 2 CTAs/SM.
//
// out[b,n,u,w,c] = AC[w,c] + (0 <= c-w < 128 ? BD[w, c-w] : 0)
// ---------------------------------------------------------------------------

namespace {
constexpr int Uu = 32, Nn = 8, Cc = 255;

constexpr int RS = 80;                    // tile row stride (words); conflict-free
constexpr int OFF_B  = 64 * RS;           // 5120   (sA: 64 rows)
constexpr int OFF_BD = OFF_B + 128 * RS;  // 15360  (sB: 128 rows)
constexpr int BDS = 136;
constexpr int SMEM_WORDS = OFF_BD + 64 * BDS;     // 24064
constexpr int SMEM_BYTES = SMEM_WORDS * 4;        // 96256  -> 2 CTAs/SM
}

// E: [f][nh]  128*512 floats = 256 KB
__device__ float g_E[128 * 512];

// ---------------------------------------------------------------------------
__device__ __forceinline__ void mma16(float* c, const uint32_t* a, const uint32_t* b) {
    asm volatile(
        "mma.sync.aligned.m16n8k16.row.col.f32.f16.f16.f32 "
        "{%0,%1,%2,%3}, {%4,%5,%6,%7}, {%8,%9}, {%0,%1,%2,%3};"
        : "+f"(c[0]), "+f"(c[1]), "+f"(c[2]), "+f"(c[3])
        : "r"(a[0]), "r"(a[1]), "r"(a[2]), "r"(a[3]), "r"(b[0]), "r"(b[1]));
}

__device__ __forceinline__ uint32_t pack_h2(float a, float b) {
    __half2 h = __floats2half2_rn(a, b);
    return *reinterpret_cast<uint32_t*>(&h);
}

// store one k-pair (p = k/2) as fused hi/lo words, fragment-permuted.
__device__ __forceinline__ void pack_pair(uint32_t* __restrict__ rowp, int p,
                                          float e0, float e1) {
    int kb = p >> 3, pp = p & 7;
    int pprime = ((pp & 3) << 1) | (pp >> 2);
    int wi = kb * 16 + (pprime << 1);
    __half h0 = __float2half_rn(e0), h1 = __float2half_rn(e1);
    rowp[wi]     = pack_h2(__half2float(h0), __half2float(h1));
    rowp[wi + 1] = pack_h2(e0 - __half2float(h0), e1 - __half2float(h1));
}

__device__ __forceinline__ void pack4(uint32_t* __restrict__ rowp, int h4, float4 v) {
    pack_pair(rowp, (h4 >> 1),     v.x, v.y);
    pack_pair(rowp, (h4 >> 1) + 1, v.z, v.w);
}

// 16x32 warp-tile gemm over K=64, 3x fp16 split.
__device__ __forceinline__ void gemm_warp(const uint32_t* __restrict__ sA,
                                          const uint32_t* __restrict__ sB,
                                          float acc[4][4],
                                          int rm, int cn, int g, int t) {
    #pragma unroll
    for (int kb = 0; kb < 4; ++kb) {
        const int ko = kb * 16 + 4 * t;
        const uint4 x0 = *(const uint4*)&sA[(rm + g) * RS + ko];
        const uint4 x1 = *(const uint4*)&sA[(rm + g + 8) * RS + ko];
        uint32_t aH[4] = {x0.x, x1.x, x0.z, x1.z};
        uint32_t aL[4] = {x0.y, x1.y, x0.w, x1.w};
        #pragma unroll
        for (int j = 0; j < 4; ++j) {
            const uint4 fb = *(const uint4*)&sB[(cn + 8 * j + g) * RS + ko];
            uint32_t bH[2] = {fb.x, fb.z};
            uint32_t bL[2] = {fb.y, fb.w};
            mma16(acc[j], aH, bH);
            mma16(acc[j], aH, bL);
            mma16(acc[j], aL, bH);
        }
    }
}

// ---------------------------------------------------------------------------
// E kernel: grid 128 = (64 f-pairs) x (2 nh-halves), 1024 threads.
// ---------------------------------------------------------------------------
__global__ __launch_bounds__(1024)
void compute_E_kernel(const float* __restrict__ pk) {
    __shared__ float sig[2 * 512];
    __shared__ float sp[16 * 2 * 256];

    const int fg  = blockIdx.x & 63;
    const int nhh = blockIdx.x >> 6;
    const int f2  = fg * 2;
    const int nh0 = nhh * 256;
    const int tid = threadIdx.x;
    const float log_inc = 9.210340371976184f / 255.0f;

    {
        int fi = tid >> 9, d = tid & 511, j = d & 255;
        float arg = (float)(127 - (f2 + fi)) * expf(-(float)j * log_inc);
        sig[fi * 512 + d] = (d < 256) ? sinf(arg) : cosf(arg);
    }
    __syncthreads();

    const int q = tid & 63, ch = tid >> 6;
    const float* p = pk + (size_t)(ch * 32) * 512 + nh0 + 4 * q;
    float4 a0 = make_float4(0.f, 0.f, 0.f, 0.f);
    float4 a1 = make_float4(0.f, 0.f, 0.f, 0.f);
    #pragma unroll
    for (int dd = 0; dd < 32; ++dd) {
        float4 v = __ldg((const float4*)(p + (size_t)dd * 512));
        int d = ch * 32 + dd;
        float s0 = sig[d], s1 = sig[512 + d];
        a0.x = fmaf(s0, v.x, a0.x); a0.y = fmaf(s0, v.y, a0.y);
        a0.z = fmaf(s0, v.z, a0.z); a0.w = fmaf(s0, v.w, a0.w);
        a1.x = fmaf(s1, v.x, a1.x); a1.y = fmaf(s1, v.y, a1.y);
        a1.z = fmaf(s1, v.z, a1.z); a1.w = fmaf(s1, v.w, a1.w);
    }
    *(float4*)&sp[(ch * 2 + 0) * 256 + 4 * q] = a0;
    *(float4*)&sp[(ch * 2 + 1) * 256 + 4 * q] = a1;
    __syncthreads();

    if (tid < 128) {
        int fi = tid >> 6, qq = tid & 63;
        float4 s = make_float4(0.f, 0.f, 0.f, 0.f);
        #pragma unroll
        for (int c = 0; c < 16; ++c) {
            float4 v = *(const float4*)&sp[(c * 2 + fi) * 256 + 4 * qq];
            s.x += v.x; s.y += v.y; s.z += v.z; s.w += v.w;
        }
        *(float4*)&g_E[(f2 + fi) * 512 + nh0 + 4 * qq] = s;
    }
}

// ---------------------------------------------------------------------------
// Main kernel: one CTA per (b,u,n,mh), 512 threads (16 warps, 4m x 4n).
// ---------------------------------------------------------------------------
__global__ __launch_bounds__(512, 2)
void txl_mma_kernel(const float* __restrict__ q_g,
                    const float* __restrict__ k_g,
                    float* __restrict__ out_g) {
    extern __shared__ uint32_t sm[];
    uint32_t* sA = sm;
    uint32_t* sB = sm + OFF_B;
    float* sBD = reinterpret_cast<float*>(sm + OFF_BD);

    const int tid = threadIdx.x;
    const int lane = tid & 31, wid = tid >> 5;
    const int wm = wid & 3, wn = wid >> 2;
    const int g = lane >> 2, t = lane & 3;

    const int bid = blockIdx.x;
    const int mh = bid & 1;
    const int n = (bid >> 1) & 7, u = (bid >> 4) & 31, b = bid >> 9;

    const float* Q  = q_g + (size_t)(b * Uu + u) * 128 * 512 + (size_t)mh * 64 * 512 + n * 64;
    const float* Kg = k_g + (size_t)(b * Uu + u) * Cc * 512 + n * 64;
    float* OUT = out_g + (size_t)((b * Nn + n) * Uu + u) * 128 * Cc + (size_t)mh * 64 * Cc;

    const int prow = tid >> 4;             // pack row (it=0)
    const int ph4  = (tid & 15) << 2;

    // ---- pack Q(64 rows) -> sA, E(128) -> sB; prefetch K0 -> regs ----
    float4 kreg[4];
    #pragma unroll
    for (int it = 0; it < 2; ++it) {
        const int row = prow + 32 * it;
        float4 qv = *(const float4*)&Q[(size_t)row * 512 + ph4];
        pack4(sA + row * RS, ph4, qv);
    }
    #pragma unroll
    for (int it = 0; it < 4; ++it) {
        const int row = prow + 32 * it;
        float4 ev = *(const float4*)&g_E[row * 512 + n * 64 + ph4];
        pack4(sB + row * RS, ph4, ev);
        kreg[it] = *(const float4*)&Kg[(size_t)row * 512 + ph4];
    }
    __syncthreads();

    // ---- BD = Q @ E^T ----
    {
        float accbd[4][4];
        #pragma unroll
        for (int j = 0; j < 4; ++j)
            #pragma unroll
            for (int e = 0; e < 4; ++e) accbd[j][e] = 0.f;
        gemm_warp(sA, sB, accbd, 16 * wm, 32 * wn, g, t);
        __syncthreads();                       // E reads complete

        // pack K0 -> sB; stage BD -> sBD
        #pragma unroll
        for (int it = 0; it < 4; ++it)
            pack4(sB + (prow + 32 * it) * RS, ph4, kreg[it]);
        #pragma unroll
        for (int j = 0; j < 4; ++j) {
            const int lw = 16 * wm + g;
            const int f0 = 32 * wn + 8 * j + 2 * t;
            *(float2*)&sBD[lw * BDS + f0] = make_float2(accbd[j][0], accbd[j][1]);
            *(float2*)&sBD[(lw + 8) * BDS + f0] = make_float2(accbd[j][2], accbd[j][3]);
        }
    }
    __syncthreads();

    // ---- AC halves ----
    #pragma unroll 1
    for (int half = 0; half < 2; ++half) {
        float acc[4][4];
        #pragma unroll
        for (int j = 0; j < 4; ++j)
            #pragma unroll
            for (int e = 0; e < 4; ++e) acc[j][e] = 0.f;
        gemm_warp(sA, sB, acc, 16 * wm, 32 * wn, g, t);

        if (half == 0) {
            // issue K1 loads; latency hides under the epilogue below
            #pragma unroll
            for (int it = 0; it < 4; ++it) {
                const int c = 128 + prow + 32 * it;
                kreg[it] = (c < Cc) ? *(const float4*)&Kg[(size_t)c * 512 + ph4]
                                    : make_float4(0.f, 0.f, 0.f, 0.f);
            }
        }

        // epilogue: add shifted BD, direct stores
        #pragma unroll
        for (int j = 0; j < 4; ++j) {
            const int c0 = 128 * half + 32 * wn + 8 * j + 2 * t;
            #pragma unroll
            for (int p = 0; p < 2; ++p) {
                const int lw = 16 * wm + g + 8 * p;       // local row
                const int wg = mh * 64 + lw;              // global row
                float v0 = acc[j][2 * p];
                float v1 = acc[j][2 * p + 1];
                const int f = c0 - wg;
                if (f >= 0 && f < 128)          v0 += sBD[lw * BDS + f];
                if (f + 1 >= 0 && f + 1 < 128)  v1 += sBD[lw * BDS + f + 1];
                float* o = &OUT[(size_t)lw * Cc + c0];
                o[0] = v0;
                if (c0 + 1 < Cc) o[1] = v1;
            }
        }

        if (half == 0) {
            __syncthreads();                   // AC0 fragment reads complete
            #pragma unroll
            for (int it = 0; it < 4; ++it)
                pack4(sB + (prow + 32 * it) * RS, ph4, kreg[it]);
            __syncthreads();
        }
    }
}

// ---------------------------------------------------------------------------
extern "C" void kernel_launch(void* const* d_in, const int* in_sizes, int n_in,
                              void* d_out, int out_size) {
    (void)in_sizes; (void)n_in; (void)out_size;
    const float* q  = (const float*)d_in[0];   // queries (4,32,128,8,64)
    const float* k  = (const float*)d_in[1];   // keys    (4,32,255,8,64)
    const float* pk = (const float*)d_in[2];   // pos_kernel (512,8,64)
    float* out = (float*)d_out;                // (4,8,32,128,255)

    compute_E_kernel<<<128, 1024>>>(pk);

    cudaFuncSetAttribute(txl_mma_kernel,
                         cudaFuncAttributeMaxDynamicSharedMemorySize, SMEM_BYTES);
    txl_mma_kernel<<<2 * 4 * Uu * Nn, 512, SMEM_BYTES>>>(q, k, out);
}

// round 7
// speedup vs baseline: 2.9033x; 1.0638x over previous
#include <cuda_runtime.h>
#include <cuda_fp16.h>
#include <cstdint>

// ---------------------------------------------------------------------------
// TransformerXL relative position embedding — fp16 3x-split mma.sync m16n8k16
// Split-M CTAs (M=64), 256 threads, 32x32 warp tiles, 2 CTAs/SM.
//
// out[b,n,u,w,c] = AC[w,c] + (0 <= c-w < 128 ? BD[w, c-w] : 0)
// ---------------------------------------------------------------------------

namespace {
constexpr int Uu = 32, Nn = 8, Cc = 255;

constexpr int RS = 80;                    // tile row stride (words); conflict-free
constexpr int OFF_B  = 64 * RS;           // sA: 64 rows
constexpr int OFF_BD = OFF_B + 128 * RS;  // sB: 128 rows
constexpr int BDS = 136;
constexpr int SMEM_WORDS = OFF_BD + 64 * BDS;     // 24064
constexpr int SMEM_BYTES = SMEM_WORDS * 4;        // 96256 -> 2 CTAs/SM
}

// E pre-packed in fused hi/lo fragment layout: [n][f][64 words] = 256 KB
__device__ uint32_t g_Epk[Nn * 128 * 64];

// ---------------------------------------------------------------------------
__device__ __forceinline__ void mma16(float* c, const uint32_t* a, const uint32_t* b) {
    asm volatile(
        "mma.sync.aligned.m16n8k16.row.col.f32.f16.f16.f32 "
        "{%0,%1,%2,%3}, {%4,%5,%6,%7}, {%8,%9}, {%0,%1,%2,%3};"
        : "+f"(c[0]), "+f"(c[1]), "+f"(c[2]), "+f"(c[3])
        : "r"(a[0]), "r"(a[1]), "r"(a[2]), "r"(a[3]), "r"(b[0]), "r"(b[1]));
}

__device__ __forceinline__ uint32_t pack_h2(float a, float b) {
    __half2 h = __floats2half2_rn(a, b);
    return *reinterpret_cast<uint32_t*>(&h);
}

// store one k-pair (p = k/2) as fused hi/lo words, fragment-permuted.
__device__ __forceinline__ void pack_pair(uint32_t* __restrict__ rowp, int p,
                                          float e0, float e1) {
    int kb = p >> 3, pp = p & 7;
    int pprime = ((pp & 3) << 1) | (pp >> 2);
    int wi = kb * 16 + (pprime << 1);
    __half h0 = __float2half_rn(e0), h1 = __float2half_rn(e1);
    rowp[wi]     = pack_h2(__half2float(h0), __half2float(h1));
    rowp[wi + 1] = pack_h2(e0 - __half2float(h0), e1 - __half2float(h1));
}

__device__ __forceinline__ void pack4(uint32_t* __restrict__ rowp, int h4, float4 v) {
    pack_pair(rowp, (h4 >> 1),     v.x, v.y);
    pack_pair(rowp, (h4 >> 1) + 1, v.z, v.w);
}

__device__ __forceinline__ void cp16(uint32_t dst, const void* src) {
    asm volatile("cp.async.ca.shared.global [%0], [%1], 16;" :: "r"(dst), "l"(src));
}

// 32x32 warp-tile gemm over K=64, 3x fp16 split.
__device__ __forceinline__ void gemm_warp(const uint32_t* __restrict__ sA,
                                          const uint32_t* __restrict__ sB,
                                          float acc[2][4][4],
                                          int rm, int cn, int g, int t) {
    #pragma unroll
    for (int kb = 0; kb < 4; ++kb) {
        const int ko = kb * 16 + 4 * t;
        const uint4 x0 = *(const uint4*)&sA[(rm + g) * RS + ko];
        const uint4 x1 = *(const uint4*)&sA[(rm + g + 8) * RS + ko];
        const uint4 x2 = *(const uint4*)&sA[(rm + 16 + g) * RS + ko];
        const uint4 x3 = *(const uint4*)&sA[(rm + 24 + g) * RS + ko];
        uint32_t aH[2][4] = {{x0.x, x1.x, x0.z, x1.z}, {x2.x, x3.x, x2.z, x3.z}};
        uint32_t aL[2][4] = {{x0.y, x1.y, x0.w, x1.w}, {x2.y, x3.y, x2.w, x3.w}};
        #pragma unroll
        for (int j = 0; j < 4; ++j) {
            const uint4 fb = *(const uint4*)&sB[(cn + 8 * j + g) * RS + ko];
            uint32_t bH[2] = {fb.x, fb.z};
            uint32_t bL[2] = {fb.y, fb.w};
            #pragma unroll
            for (int i = 0; i < 2; ++i) {
                mma16(acc[i][j], aH[i], bH);
                mma16(acc[i][j], aH[i], bL);
                mma16(acc[i][j], aL[i], bH);
            }
        }
    }
}

// ---------------------------------------------------------------------------
// E kernel: grid 128 = (64 f-pairs) x (2 nh-halves), 1024 threads.
// Writes E directly in the packed fragment layout.
// ---------------------------------------------------------------------------
__global__ __launch_bounds__(1024)
void compute_E_kernel(const float* __restrict__ pk) {
    __shared__ float sig[2 * 512];
    __shared__ float sp[16 * 2 * 256];

    const int fg  = blockIdx.x & 63;
    const int nhh = blockIdx.x >> 6;
    const int f2  = fg * 2;
    const int nh0 = nhh * 256;
    const int tid = threadIdx.x;
    const float log_inc = 9.210340371976184f / 255.0f;

    {
        int fi = tid >> 9, d = tid & 511, j = d & 255;
        float arg = (float)(127 - (f2 + fi)) * expf(-(float)j * log_inc);
        sig[fi * 512 + d] = (d < 256) ? sinf(arg) : cosf(arg);
    }
    __syncthreads();

    const int q = tid & 63, ch = tid >> 6;
    const float* p = pk + (size_t)(ch * 32) * 512 + nh0 + 4 * q;
    float4 a0 = make_float4(0.f, 0.f, 0.f, 0.f);
    float4 a1 = make_float4(0.f, 0.f, 0.f, 0.f);
    #pragma unroll
    for (int dd = 0; dd < 32; ++dd) {
        float4 v = __ldg((const float4*)(p + (size_t)dd * 512));
        int d = ch * 32 + dd;
        float s0 = sig[d], s1 = sig[512 + d];
        a0.x = fmaf(s0, v.x, a0.x); a0.y = fmaf(s0, v.y, a0.y);
        a0.z = fmaf(s0, v.z, a0.z); a0.w = fmaf(s0, v.w, a0.w);
        a1.x = fmaf(s1, v.x, a1.x); a1.y = fmaf(s1, v.y, a1.y);
        a1.z = fmaf(s1, v.z, a1.z); a1.w = fmaf(s1, v.w, a1.w);
    }
    *(float4*)&sp[(ch * 2 + 0) * 256 + 4 * q] = a0;
    *(float4*)&sp[(ch * 2 + 1) * 256 + 4 * q] = a1;
    __syncthreads();

    if (tid < 128) {
        int fi = tid >> 6, qq = tid & 63;
        float4 s = make_float4(0.f, 0.f, 0.f, 0.f);
        #pragma unroll
        for (int c = 0; c < 16; ++c) {
            float4 v = *(const float4*)&sp[(c * 2 + fi) * 256 + 4 * qq];
            s.x += v.x; s.y += v.y; s.z += v.z; s.w += v.w;
        }
        const int n  = nhh * 4 + (qq >> 4);
        const int h4 = (4 * qq) & 63;
        pack4(g_Epk + n * (128 * 64) + (f2 + fi) * 64, h4, s);
    }
}

// ---------------------------------------------------------------------------
// Main kernel: one CTA per (b,u,n,mh), 256 threads (8 warps, 2m x 4n).
// ---------------------------------------------------------------------------
__global__ __launch_bounds__(256, 2)
void txl_mma_kernel(const float* __restrict__ q_g,
                    const float* __restrict__ k_g,
                    float* __restrict__ out_g) {
    extern __shared__ uint32_t sm[];
    uint32_t* sA = sm;
    uint32_t* sB = sm + OFF_B;
    float* sBD = reinterpret_cast<float*>(sm + OFF_BD);

    const int tid = threadIdx.x;
    const int lane = tid & 31, wid = tid >> 5;
    const int wm = wid & 1, wn = wid >> 1;
    const int g = lane >> 2, t = lane & 3;

    const int bid = blockIdx.x;
    const int mh = bid & 1;
    const int n = (bid >> 1) & 7, u = (bid >> 4) & 31, b = bid >> 9;

    const float* Q  = q_g + (size_t)(b * Uu + u) * 128 * 512 + (size_t)mh * 64 * 512 + n * 64;
    const float* Kg = k_g + (size_t)(b * Uu + u) * Cc * 512 + n * 64;
    float* OUT = out_g + (size_t)((b * Nn + n) * Uu + u) * 128 * Cc + (size_t)mh * 64 * Cc;

    const int prow = tid >> 4;             // 0..15
    const int ph4  = (tid & 15) << 2;

    // ---- E -> sB via cp.async (already packed) ----
    {
        uint32_t sB_u32;
        asm("{ .reg .u64 t; cvta.to.shared.u64 t, %1; cvt.u32.u64 %0, t; }"
            : "=r"(sB_u32) : "l"(sB));
        const uint32_t* Ep = g_Epk + n * (128 * 64);
        #pragma unroll
        for (int i = 0; i < 8; ++i) {
            int idx = tid + 256 * i;           // 0..2047
            int r = idx >> 4, w4 = (idx & 15) << 2;
            cp16(sB_u32 + (uint32_t)(r * RS + w4) * 4, Ep + r * 64 + w4);
        }
        asm volatile("cp.async.commit_group;");
    }

    // ---- pack Q(64 rows) -> sA; prefetch K0 (128 rows) -> regs ----
    float4 kreg[8];
    #pragma unroll
    for (int it = 0; it < 4; ++it) {
        const int row = prow + 16 * it;
        float4 qv = *(const float4*)&Q[(size_t)row * 512 + ph4];
        pack4(sA + row * RS, ph4, qv);
    }
    #pragma unroll
    for (int it = 0; it < 8; ++it)
        kreg[it] = *(const float4*)&Kg[(size_t)(prow + 16 * it) * 512 + ph4];

    asm volatile("cp.async.wait_group 0;");
    __syncthreads();

    // ---- BD = Q @ E^T ----
    {
        float accbd[2][4][4];
        #pragma unroll
        for (int i = 0; i < 2; ++i)
            #pragma unroll
            for (int j = 0; j < 4; ++j)
                #pragma unroll
                for (int e = 0; e < 4; ++e) accbd[i][j][e] = 0.f;
        gemm_warp(sA, sB, accbd, 32 * wm, 32 * wn, g, t);
        __syncthreads();                       // E reads complete

        // pack K0 -> sB; stage BD -> sBD; prefetch K1
        #pragma unroll
        for (int it = 0; it < 8; ++it)
            pack4(sB + (prow + 16 * it) * RS, ph4, kreg[it]);
        #pragma unroll
        for (int i = 0; i < 2; ++i)
            #pragma unroll
            for (int j = 0; j < 4; ++j) {
                const int lw = 32 * wm + 16 * i + g;
                const int f0 = 32 * wn + 8 * j + 2 * t;
                *(float2*)&sBD[lw * BDS + f0] = make_float2(accbd[i][j][0], accbd[i][j][1]);
                *(float2*)&sBD[(lw + 8) * BDS + f0] = make_float2(accbd[i][j][2], accbd[i][j][3]);
            }
        #pragma unroll
        for (int it = 0; it < 8; ++it) {
            const int c = 128 + prow + 16 * it;
            kreg[it] = (c < Cc) ? *(const float4*)&Kg[(size_t)c * 512 + ph4]
                                : make_float4(0.f, 0.f, 0.f, 0.f);
        }
    }
    __syncthreads();

    // ---- AC halves ----
    #pragma unroll 1
    for (int half = 0; half < 2; ++half) {
        float acc[2][4][4];
        #pragma unroll
        for (int i = 0; i < 2; ++i)
            #pragma unroll
            for (int j = 0; j < 4; ++j)
                #pragma unroll
                for (int e = 0; e < 4; ++e) acc[i][j][e] = 0.f;
        gemm_warp(sA, sB, acc, 32 * wm, 32 * wn, g, t);

        if (half == 0) {
            __syncthreads();                   // all K0 fragment reads complete
            #pragma unroll
            for (int it = 0; it < 8; ++it)
                pack4(sB + (prow + 16 * it) * RS, ph4, kreg[it]);
        }

        // epilogue: add shifted BD, direct stores
        #pragma unroll
        for (int i = 0; i < 2; ++i)
            #pragma unroll
            for (int j = 0; j < 4; ++j) {
                const int c0 = 128 * half + 32 * wn + 8 * j + 2 * t;
                #pragma unroll
                for (int p = 0; p < 2; ++p) {
                    const int lw = 32 * wm + 16 * i + g + 8 * p;  // local row
                    const int wg = mh * 64 + lw;                  // global row
                    float v0 = acc[i][j][2 * p];
                    float v1 = acc[i][j][2 * p + 1];
                    const int f = c0 - wg;
                    if (f >= 0 && f < 128)          v0 += sBD[lw * BDS + f];
                    if (f + 1 >= 0 && f + 1 < 128)  v1 += sBD[lw * BDS + f + 1];
                    float* o = &OUT[(size_t)lw * Cc + c0];
                    o[0] = v0;
                    if (c0 + 1 < Cc) o[1] = v1;
                }
            }
        if (half == 0) __syncthreads();
    }
}

// ---------------------------------------------------------------------------
extern "C" void kernel_launch(void* const* d_in, const int* in_sizes, int n_in,
                              void* d_out, int out_size) {
    (void)in_sizes; (void)n_in; (void)out_size;
    const float* q  = (const float*)d_in[0];   // queries (4,32,128,8,64)
    const float* k  = (const float*)d_in[1];   // keys    (4,32,255,8,64)
    const float* pk = (const float*)d_in[2];   // pos_kernel (512,8,64)
    float* out = (float*)d_out;                // (4,8,32,128,255)

    compute_E_kernel<<<128, 1024>>>(pk);

    cudaFuncSetAttribute(txl_mma_kernel,
                         cudaFuncAttributeMaxDynamicSharedMemorySize, SMEM_BYTES);
    txl_mma_kernel<<<2 * 4 * Uu * Nn, 256, SMEM_BYTES>>>(q, k, out);
}

// round 8
// speedup vs baseline: 3.1476x; 1.0841x over previous
#include <cuda_runtime.h>
#include <cuda_fp16.h>
#include <cstdint>

// ---------------------------------------------------------------------------
// TransformerXL relative position embedding — fp16 2x-split mma.sync m16n8k16
//   q·k ≈ qh·kh + ql·kh   (A split hi/lo, B hi only; rel_err ~1e-4 << 1e-3)
// Split-M CTAs (M=64), 256 threads, 32x32 warp tiles, 3 CTAs/SM.
//
// out[b,n,u,w,c] = AC[w,c] + (0 <= c-w < 128 ? BD[w, c-w] : 0)
// ---------------------------------------------------------------------------

namespace {
constexpr int Uu = 32, Nn = 8, Cc = 255;

constexpr int RSA = 80;                   // A row stride (words), fused hi/lo
constexpr int RSB = 40;                   // B row stride (words), hi only
constexpr int OFF_B  = 64 * RSA;          // 5120
constexpr int OFF_BD = OFF_B + 128 * RSB; // 10240
constexpr int BDS = 136;
constexpr int SMEM_WORDS = OFF_BD + 64 * BDS;   // 18944
constexpr int SMEM_BYTES = SMEM_WORDS * 4;      // 75776 -> 3 CTAs/SM
}

// E pre-packed hi-only fragment layout: [n][f][32 words] = 128 KB
__device__ uint32_t g_Epk[Nn * 128 * 32];

// ---------------------------------------------------------------------------
__device__ __forceinline__ void mma16(float* c, const uint32_t* a, const uint32_t* b) {
    asm volatile(
        "mma.sync.aligned.m16n8k16.row.col.f32.f16.f16.f32 "
        "{%0,%1,%2,%3}, {%4,%5,%6,%7}, {%8,%9}, {%0,%1,%2,%3};"
        : "+f"(c[0]), "+f"(c[1]), "+f"(c[2]), "+f"(c[3])
        : "r"(a[0]), "r"(a[1]), "r"(a[2]), "r"(a[3]), "r"(b[0]), "r"(b[1]));
}

__device__ __forceinline__ uint32_t pack_h2(float a, float b) {
    __half2 h = __floats2half2_rn(a, b);
    return *reinterpret_cast<uint32_t*>(&h);
}

// --- A (fused hi/lo, permuted): word = kb*16 + 2*pprime(p) + {0=hi,1=lo} ---
__device__ __forceinline__ void packA_pair(uint32_t* __restrict__ rowp, int p,
                                           float e0, float e1) {
    int kb = p >> 3, pp = p & 7;
    int pprime = ((pp & 3) << 1) | (pp >> 2);
    int wi = kb * 16 + (pprime << 1);
    __half h0 = __float2half_rn(e0), h1 = __float2half_rn(e1);
    rowp[wi]     = pack_h2(__half2float(h0), __half2float(h1));
    rowp[wi + 1] = pack_h2(e0 - __half2float(h0), e1 - __half2float(h1));
}
__device__ __forceinline__ void packA4(uint32_t* __restrict__ rowp, int h4, float4 v) {
    packA_pair(rowp, (h4 >> 1),     v.x, v.y);
    packA_pair(rowp, (h4 >> 1) + 1, v.z, v.w);
}

// --- B (hi only, permuted): word = kb*8 + pprime(p) ---
__device__ __forceinline__ void packB_pair(uint32_t* __restrict__ rowp, int p,
                                           float e0, float e1) {
    int kb = p >> 3, pp = p & 7;
    int pprime = ((pp & 3) << 1) | (pp >> 2);
    rowp[kb * 8 + pprime] = pack_h2(e0, e1);
}
__device__ __forceinline__ void packB4(uint32_t* __restrict__ rowp, int h4, float4 v) {
    packB_pair(rowp, (h4 >> 1),     v.x, v.y);
    packB_pair(rowp, (h4 >> 1) + 1, v.z, v.w);
}

__device__ __forceinline__ void cp16(uint32_t dst, const void* src) {
    asm volatile("cp.async.ca.shared.global [%0], [%1], 16;" :: "r"(dst), "l"(src));
}

// 32x32 warp-tile gemm over K=64, 2x fp16 split (A hi/lo, B hi).
__device__ __forceinline__ void gemm_warp(const uint32_t* __restrict__ sA,
                                          const uint32_t* __restrict__ sB,
                                          float acc[2][4][4],
                                          int rm, int cn, int g, int t) {
    #pragma unroll
    for (int kb = 0; kb < 4; ++kb) {
        const int koA = kb * 16 + 4 * t;
        const int koB = kb * 8 + 2 * t;
        const uint4 x0 = *(const uint4*)&sA[(rm + g) * RSA + koA];
        const uint4 x1 = *(const uint4*)&sA[(rm + g + 8) * RSA + koA];
        const uint4 x2 = *(const uint4*)&sA[(rm + 16 + g) * RSA + koA];
        const uint4 x3 = *(const uint4*)&sA[(rm + 24 + g) * RSA + koA];
        uint32_t aH[2][4] = {{x0.x, x1.x, x0.z, x1.z}, {x2.x, x3.x, x2.z, x3.z}};
        uint32_t aL[2][4] = {{x0.y, x1.y, x0.w, x1.w}, {x2.y, x3.y, x2.w, x3.w}};
        #pragma unroll
        for (int j = 0; j < 4; ++j) {
            const uint2 fb = *(const uint2*)&sB[(cn + 8 * j + g) * RSB + koB];
            uint32_t bH[2] = {fb.x, fb.y};
            #pragma unroll
            for (int i = 0; i < 2; ++i) {
                mma16(acc[i][j], aH[i], bH);
                mma16(acc[i][j], aL[i], bH);
            }
        }
    }
}

// ---------------------------------------------------------------------------
// E kernel: grid 128 = (64 f-pairs) x (2 nh-halves), 1024 threads.
// Writes E directly in the hi-only packed fragment layout.
// ---------------------------------------------------------------------------
__global__ __launch_bounds__(1024)
void compute_E_kernel(const float* __restrict__ pk) {
    __shared__ float sig[2 * 512];
    __shared__ float sp[16 * 2 * 256];

    const int fg  = blockIdx.x & 63;
    const int nhh = blockIdx.x >> 6;
    const int f2  = fg * 2;
    const int nh0 = nhh * 256;
    const int tid = threadIdx.x;
    const float log_inc = 9.210340371976184f / 255.0f;

    {
        int fi = tid >> 9, d = tid & 511, j = d & 255;
        float arg = (float)(127 - (f2 + fi)) * expf(-(float)j * log_inc);
        sig[fi * 512 + d] = (d < 256) ? sinf(arg) : cosf(arg);
    }
    __syncthreads();

    const int q = tid & 63, ch = tid >> 6;
    const float* p = pk + (size_t)(ch * 32) * 512 + nh0 + 4 * q;
    float4 a0 = make_float4(0.f, 0.f, 0.f, 0.f);
    float4 a1 = make_float4(0.f, 0.f, 0.f, 0.f);
    #pragma unroll
    for (int dd = 0; dd < 32; ++dd) {
        float4 v = __ldg((const float4*)(p + (size_t)dd * 512));
        int d = ch * 32 + dd;
        float s0 = sig[d], s1 = sig[512 + d];
        a0.x = fmaf(s0, v.x, a0.x); a0.y = fmaf(s0, v.y, a0.y);
        a0.z = fmaf(s0, v.z, a0.z); a0.w = fmaf(s0, v.w, a0.w);
        a1.x = fmaf(s1, v.x, a1.x); a1.y = fmaf(s1, v.y, a1.y);
        a1.z = fmaf(s1, v.z, a1.z); a1.w = fmaf(s1, v.w, a1.w);
    }
    *(float4*)&sp[(ch * 2 + 0) * 256 + 4 * q] = a0;
    *(float4*)&sp[(ch * 2 + 1) * 256 + 4 * q] = a1;
    __syncthreads();

    if (tid < 128) {
        int fi = tid >> 6, qq = tid & 63;
        float4 s = make_float4(0.f, 0.f, 0.f, 0.f);
        #pragma unroll
        for (int c = 0; c < 16; ++c) {
            float4 v = *(const float4*)&sp[(c * 2 + fi) * 256 + 4 * qq];
            s.x += v.x; s.y += v.y; s.z += v.z; s.w += v.w;
        }
        const int n  = nhh * 4 + (qq >> 4);
        const int h4 = (4 * qq) & 63;
        packB4(g_Epk + n * (128 * 32) + (f2 + fi) * 32, h4, s);
    }
}

// ---------------------------------------------------------------------------
// Main kernel: one CTA per (b,u,n,mh), 256 threads (8 warps, 2m x 4n).
// ---------------------------------------------------------------------------
__global__ __launch_bounds__(256, 3)
void txl_mma_kernel(const float* __restrict__ q_g,
                    const float* __restrict__ k_g,
                    float* __restrict__ out_g) {
    extern __shared__ uint32_t sm[];
    uint32_t* sA = sm;
    uint32_t* sB = sm + OFF_B;
    float* sBD = reinterpret_cast<float*>(sm + OFF_BD);

    const int tid = threadIdx.x;
    const int lane = tid & 31, wid = tid >> 5;
    const int wm = wid & 1, wn = wid >> 1;
    const int g = lane >> 2, t = lane & 3;

    const int bid = blockIdx.x;
    const int mh = bid & 1;
    const int n = (bid >> 1) & 7, u = (bid >> 4) & 31, b = bid >> 9;

    const float* Q  = q_g + (size_t)(b * Uu + u) * 128 * 512 + (size_t)mh * 64 * 512 + n * 64;
    const float* Kg = k_g + (size_t)(b * Uu + u) * Cc * 512 + n * 64;
    float* OUT = out_g + (size_t)((b * Nn + n) * Uu + u) * 128 * Cc + (size_t)mh * 64 * Cc;

    const int prow = tid >> 4;             // 0..15
    const int ph4  = (tid & 15) << 2;

    // ---- E -> sB via cp.async (hi-only, already packed) ----
    {
        uint32_t sB_u32;
        asm("{ .reg .u64 t; cvta.to.shared.u64 t, %1; cvt.u32.u64 %0, t; }"
            : "=r"(sB_u32) : "l"(sB));
        const uint32_t* Ep = g_Epk + n * (128 * 32);
        #pragma unroll
        for (int i = 0; i < 4; ++i) {
            int idx = tid + 256 * i;           // 0..1023 chunks of 4 words
            int r = idx >> 3, w4 = (idx & 7) << 2;
            cp16(sB_u32 + (uint32_t)(r * RSB + w4) * 4, Ep + r * 32 + w4);
        }
        asm volatile("cp.async.commit_group;");
    }

    // ---- pack Q(64 rows) -> sA; prefetch K rows 0..63 ----
    float4 kreg[4];
    #pragma unroll
    for (int it = 0; it < 4; ++it) {
        const int row = prow + 16 * it;
        float4 qv = *(const float4*)&Q[(size_t)row * 512 + ph4];
        packA4(sA + row * RSA, ph4, qv);
        kreg[it] = *(const float4*)&Kg[(size_t)row * 512 + ph4];
    }
    asm volatile("cp.async.wait_group 0;");
    __syncthreads();

    // ---- BD = Q @ E^T ----
    {
        float accbd[2][4][4] = {};
        gemm_warp(sA, sB, accbd, 32 * wm, 32 * wn, g, t);
        __syncthreads();                       // E reads complete

        // pack K rows 0..63; load K rows 64..127; stage BD -> sBD
        #pragma unroll
        for (int it = 0; it < 4; ++it)
            packB4(sB + (prow + 16 * it) * RSB, ph4, kreg[it]);
        #pragma unroll
        for (int it = 0; it < 4; ++it)
            kreg[it] = *(const float4*)&Kg[(size_t)(64 + prow + 16 * it) * 512 + ph4];
        #pragma unroll
        for (int i = 0; i < 2; ++i)
            #pragma unroll
            for (int j = 0; j < 4; ++j) {
                const int lw = 32 * wm + 16 * i + g;
                const int f0 = 32 * wn + 8 * j + 2 * t;
                *(float2*)&sBD[lw * BDS + f0] = make_float2(accbd[i][j][0], accbd[i][j][1]);
                *(float2*)&sBD[(lw + 8) * BDS + f0] = make_float2(accbd[i][j][2], accbd[i][j][3]);
            }
        #pragma unroll
        for (int it = 0; it < 4; ++it)
            packB4(sB + (64 + prow + 16 * it) * RSB, ph4, kreg[it]);
    }
    __syncthreads();

    // ---- AC halves ----
    #pragma unroll 1
    for (int half = 0; half < 2; ++half) {
        float acc[2][4][4] = {};
        gemm_warp(sA, sB, acc, 32 * wm, 32 * wn, g, t);

        if (half == 0) {
            // prefetch K1 rows 128..191 while epilogue runs
            #pragma unroll
            for (int it = 0; it < 4; ++it)
                kreg[it] = *(const float4*)&Kg[(size_t)(128 + prow + 16 * it) * 512 + ph4];
        }

        // epilogue: add shifted BD, direct stores
        #pragma unroll
        for (int i = 0; i < 2; ++i)
            #pragma unroll
            for (int j = 0; j < 4; ++j) {
                const int c0 = 128 * half + 32 * wn + 8 * j + 2 * t;
                #pragma unroll
                for (int p = 0; p < 2; ++p) {
                    const int lw = 32 * wm + 16 * i + g + 8 * p;  // local row
                    const int wg = mh * 64 + lw;                  // global row
                    float v0 = acc[i][j][2 * p];
                    float v1 = acc[i][j][2 * p + 1];
                    const int f = c0 - wg;
                    if (f >= 0 && f < 128)          v0 += sBD[lw * BDS + f];
                    if (f + 1 >= 0 && f + 1 < 128)  v1 += sBD[lw * BDS + f + 1];
                    float* o = &OUT[(size_t)lw * Cc + c0];
                    o[0] = v0;
                    if (c0 + 1 < Cc) o[1] = v1;
                }
            }

        if (half == 0) {
            __syncthreads();                   // K0 fragment reads complete
            #pragma unroll
            for (int it = 0; it < 4; ++it)
                packB4(sB + (prow + 16 * it) * RSB, ph4, kreg[it]);
            // load + pack K1 rows 192..255 (row 255 zero)
            #pragma unroll
            for (int it = 0; it < 4; ++it) {
                const int c = 192 + prow + 16 * it;
                kreg[it] = (c < Cc) ? *(const float4*)&Kg[(size_t)c * 512 + ph4]
                                    : make_float4(0.f, 0.f, 0.f, 0.f);
            }
            #pragma unroll
            for (int it = 0; it < 4; ++it)
                packB4(sB + (64 + prow + 16 * it) * RSB, ph4, kreg[it]);
            __syncthreads();
        }
    }
}

// ---------------------------------------------------------------------------
extern "C" void kernel_launch(void* const* d_in, const int* in_sizes, int n_in,
                              void* d_out, int out_size) {
    (void)in_sizes; (void)n_in; (void)out_size;
    const float* q  = (const float*)d_in[0];   // queries (4,32,128,8,64)
    const float* k  = (const float*)d_in[1];   // keys    (4,32,255,8,64)
    const float* pk = (const float*)d_in[2];   // pos_kernel (512,8,64)
    float* out = (float*)d_out;                // (4,8,32,128,255)

    compute_E_kernel<<<128, 1024>>>(pk);

    cudaFuncSetAttribute(txl_mma_kernel,
                         cudaFuncAttributeMaxDynamicSharedMemorySize, SMEM_BYTES);
    txl_mma_kernel<<<2 * 4 * Uu * Nn, 256, SMEM_BYTES>>>(q, k, out);
}

// round 9
// speedup vs baseline: 3.6807x; 1.1694x over previous
#include <cuda_runtime.h>
#include <cuda_fp16.h>
#include <cstdint>

// ---------------------------------------------------------------------------
// TransformerXL relative position embedding — pure fp16 mma.sync m16n8k16
//   q·k ≈ qh·kh  (both operands fp16-rounded; measured-model rel_err ~3e-4)
// Split-M CTAs (M=64), 256 threads, 32x32 warp tiles, 3 CTAs/SM.
//
// out[b,n,u,w,c] = AC[w,c] + (0 <= c-w < 128 ? BD[w, c-w] : 0)
// ---------------------------------------------------------------------------

namespace {
constexpr int Uu = 32, Nn = 8, Cc = 255;

constexpr int RS = 40;                    // row stride (words); 40%32=8 -> conflict-free
constexpr int OFF_B  = 64 * RS;           // 2560   (sA: 64 rows x 32 words hi-only)
constexpr int OFF_BD = OFF_B + 128 * RS;  // 7680   (sB: 128 rows)
constexpr int BDS = 136;
constexpr int SMEM_WORDS = OFF_BD + 64 * BDS;   // 16384
constexpr int SMEM_BYTES = SMEM_WORDS * 4;      // 65536 -> 3 CTAs/SM
}

// E pre-packed hi-only fragment layout: [n][f][32 words] = 128 KB
__device__ uint32_t g_Epk[Nn * 128 * 32];

// ---------------------------------------------------------------------------
__device__ __forceinline__ void mma16(float* c, const uint32_t* a, const uint32_t* b) {
    asm volatile(
        "mma.sync.aligned.m16n8k16.row.col.f32.f16.f16.f32 "
        "{%0,%1,%2,%3}, {%4,%5,%6,%7}, {%8,%9}, {%0,%1,%2,%3};"
        : "+f"(c[0]), "+f"(c[1]), "+f"(c[2]), "+f"(c[3])
        : "r"(a[0]), "r"(a[1]), "r"(a[2]), "r"(a[3]), "r"(b[0]), "r"(b[1]));
}

__device__ __forceinline__ uint32_t pack_h2(float a, float b) {
    __half2 h = __floats2half2_rn(a, b);
    return *reinterpret_cast<uint32_t*>(&h);
}

// --- permuted word index within a row: word = kb*8 + pprime(p), p = k/2 ---
__device__ __forceinline__ void packB_pair(uint32_t* __restrict__ rowp, int p,
                                           float e0, float e1) {
    int kb = p >> 3, pp = p & 7;
    int pprime = ((pp & 3) << 1) | (pp >> 2);
    rowp[kb * 8 + pprime] = pack_h2(e0, e1);
}
__device__ __forceinline__ void packB4(uint32_t* __restrict__ rowp, int h4, float4 v) {
    packB_pair(rowp, (h4 >> 1),     v.x, v.y);
    packB_pair(rowp, (h4 >> 1) + 1, v.z, v.w);
}

// quad-pack: v0 = row[hb..hb+3], v1 = row[hb+8..hb+11]  ->  4 adjacent words
__device__ __forceinline__ uint4 pack_quad(float4 v0, float4 v1) {
    uint4 r;
    r.x = pack_h2(v0.x, v0.y);
    r.y = pack_h2(v1.x, v1.y);
    r.z = pack_h2(v0.z, v0.w);
    r.w = pack_h2(v1.z, v1.w);
    return r;
}

__device__ __forceinline__ void cp16(uint32_t dst, const void* src) {
    asm volatile("cp.async.ca.shared.global [%0], [%1], 16;" :: "r"(dst), "l"(src));
}

// 32x32 warp-tile gemm over K=64, pure fp16.
__device__ __forceinline__ void gemm_warp(const uint32_t* __restrict__ sA,
                                          const uint32_t* __restrict__ sB,
                                          float acc[2][4][4],
                                          int rm, int cn, int g, int t) {
    #pragma unroll
    for (int kb = 0; kb < 4; ++kb) {
        const int ko = kb * 8 + 2 * t;
        const uint2 x0 = *(const uint2*)&sA[(rm + g) * RS + ko];
        const uint2 x1 = *(const uint2*)&sA[(rm + g + 8) * RS + ko];
        const uint2 x2 = *(const uint2*)&sA[(rm + 16 + g) * RS + ko];
        const uint2 x3 = *(const uint2*)&sA[(rm + 24 + g) * RS + ko];
        uint32_t a[2][4] = {{x0.x, x1.x, x0.y, x1.y}, {x2.x, x3.x, x2.y, x3.y}};
        #pragma unroll
        for (int j = 0; j < 4; ++j) {
            const uint2 fb = *(const uint2*)&sB[(cn + 8 * j + g) * RS + ko];
            uint32_t bb[2] = {fb.x, fb.y};
            mma16(acc[0][j], a[0], bb);
            mma16(acc[1][j], a[1], bb);
        }
    }
}

// ---------------------------------------------------------------------------
// E kernel: grid 128 = (64 f-pairs) x (2 nh-halves), 1024 threads.
// Writes E directly in the hi-only packed fragment layout.
// ---------------------------------------------------------------------------
__global__ __launch_bounds__(1024)
void compute_E_kernel(const float* __restrict__ pk) {
    __shared__ float sig[2 * 512];
    __shared__ float sp[16 * 2 * 256];

    const int fg  = blockIdx.x & 63;
    const int nhh = blockIdx.x >> 6;
    const int f2  = fg * 2;
    const int nh0 = nhh * 256;
    const int tid = threadIdx.x;
    const float log_inc = 9.210340371976184f / 255.0f;

    {
        int fi = tid >> 9, d = tid & 511, j = d & 255;
        float arg = (float)(127 - (f2 + fi)) * expf(-(float)j * log_inc);
        sig[fi * 512 + d] = (d < 256) ? sinf(arg) : cosf(arg);
    }
    __syncthreads();

    const int q = tid & 63, ch = tid >> 6;
    const float* p = pk + (size_t)(ch * 32) * 512 + nh0 + 4 * q;
    float4 a0 = make_float4(0.f, 0.f, 0.f, 0.f);
    float4 a1 = make_float4(0.f, 0.f, 0.f, 0.f);
    #pragma unroll
    for (int dd = 0; dd < 32; ++dd) {
        float4 v = __ldg((const float4*)(p + (size_t)dd * 512));
        int d = ch * 32 + dd;
        float s0 = sig[d], s1 = sig[512 + d];
        a0.x = fmaf(s0, v.x, a0.x); a0.y = fmaf(s0, v.y, a0.y);
        a0.z = fmaf(s0, v.z, a0.z); a0.w = fmaf(s0, v.w, a0.w);
        a1.x = fmaf(s1, v.x, a1.x); a1.y = fmaf(s1, v.y, a1.y);
        a1.z = fmaf(s1, v.z, a1.z); a1.w = fmaf(s1, v.w, a1.w);
    }
    *(float4*)&sp[(ch * 2 + 0) * 256 + 4 * q] = a0;
    *(float4*)&sp[(ch * 2 + 1) * 256 + 4 * q] = a1;
    __syncthreads();

    if (tid < 128) {
        int fi = tid >> 6, qq = tid & 63;
        float4 s = make_float4(0.f, 0.f, 0.f, 0.f);
        #pragma unroll
        for (int c = 0; c < 16; ++c) {
            float4 v = *(const float4*)&sp[(c * 2 + fi) * 256 + 4 * qq];
            s.x += v.x; s.y += v.y; s.z += v.z; s.w += v.w;
        }
        const int n  = nhh * 4 + (qq >> 4);
        const int h4 = (4 * qq) & 63;
        packB4(g_Epk + n * (128 * 32) + (f2 + fi) * 32, h4, s);
    }
}

// ---------------------------------------------------------------------------
// Main kernel: one CTA per (b,u,n,mh), 256 threads (8 warps, 2m x 4n).
// ---------------------------------------------------------------------------
__global__ __launch_bounds__(256, 3)
void txl_mma_kernel(const float* __restrict__ q_g,
                    const float* __restrict__ k_g,
                    float* __restrict__ out_g) {
    extern __shared__ uint32_t sm[];
    uint32_t* sA = sm;
    uint32_t* sB = sm + OFF_B;
    float* sBD = reinterpret_cast<float*>(sm + OFF_BD);

    const int tid = threadIdx.x;
    const int lane = tid & 31, wid = tid >> 5;
    const int wm = wid & 1, wn = wid >> 1;
    const int g = lane >> 2, t = lane & 3;

    const int bid = blockIdx.x;
    const int mh = bid & 1;
    const int n = (bid >> 1) & 7, u = (bid >> 4) & 31, b = bid >> 9;

    const float* Q  = q_g + (size_t)(b * Uu + u) * 128 * 512 + (size_t)mh * 64 * 512 + n * 64;
    const float* Kg = k_g + (size_t)(b * Uu + u) * Cc * 512 + n * 64;
    float* OUT = out_g + (size_t)((b * Nn + n) * Uu + u) * 128 * Cc + (size_t)mh * 64 * Cc;

    // per-thread pack task (within one 64-row half): row, kb, hh
    const int krow = tid >> 2;               // 0..63
    const int kkb  = (tid >> 1) & 1;         // kb pair selector (see loops)
    (void)kkb;

    // ---- E -> sB via cp.async (hi-only, already packed) ----
    {
        uint32_t sB_u32;
        asm("{ .reg .u64 t; cvta.to.shared.u64 t, %1; cvt.u32.u64 %0, t; }"
            : "=r"(sB_u32) : "l"(sB));
        const uint32_t* Ep = g_Epk + n * (128 * 32);
        #pragma unroll
        for (int i = 0; i < 4; ++i) {
            int idx = tid + 256 * i;           // 0..1023
            int r = idx >> 3, w4 = (idx & 7) << 2;
            cp16(sB_u32 + (uint32_t)(r * RS + w4) * 4, Ep + r * 32 + w4);
        }
        asm volatile("cp.async.commit_group;");
    }

    // ---- pack Q (64 rows, hi-only) -> sA ----
    // task idx: row = idx>>3, kb = (idx>>1)&3, hh = idx&1 ; 512 tasks, 2 iters
    #pragma unroll
    for (int it = 0; it < 2; ++it) {
        const int idx = tid + 256 * it;
        const int row = idx >> 3, kb = (idx >> 1) & 3, hh = idx & 1;
        const int hb = 16 * kb + 4 * hh;
        float4 v0 = *(const float4*)&Q[(size_t)row * 512 + hb];
        float4 v1 = *(const float4*)&Q[(size_t)row * 512 + hb + 8];
        *(uint4*)&sA[row * RS + kb * 8 + 4 * hh] = pack_quad(v0, v1);
    }

    // ---- gather K rows 0..63 into regs (half 1 of K0) ----
    float4 kr[4];
    #pragma unroll
    for (int jj = 0; jj < 2; ++jj) {
        const int idx = tid + 256 * jj;        // 0..511 -> rows 0..63
        const int row = idx >> 3, kb = (idx >> 1) & 3, hh = idx & 1;
        const int hb = 16 * kb + 4 * hh;
        kr[2 * jj]     = *(const float4*)&Kg[(size_t)row * 512 + hb];
        kr[2 * jj + 1] = *(const float4*)&Kg[(size_t)row * 512 + hb + 8];
    }

    asm volatile("cp.async.wait_group 0;");
    __syncthreads();

    // ---- BD = Q @ E^T ----
    float accbd[2][4][4] = {};
    gemm_warp(sA, sB, accbd, 32 * wm, 32 * wn, g, t);
    __syncthreads();                           // E reads complete

    // ---- K0: store half1, gather+store half2; stage BD -> sBD ----
    #pragma unroll
    for (int jj = 0; jj < 2; ++jj) {
        const int idx = tid + 256 * jj;
        const int row = idx >> 3, kb = (idx >> 1) & 3, hh = idx & 1;
        *(uint4*)&sB[row * RS + kb * 8 + 4 * hh] = pack_quad(kr[2 * jj], kr[2 * jj + 1]);
    }
    #pragma unroll
    for (int jj = 0; jj < 2; ++jj) {
        const int idx = tid + 256 * jj;
        const int row = 64 + (idx >> 3), kb = (idx >> 1) & 3, hh = idx & 1;
        const int hb = 16 * kb + 4 * hh;
        kr[2 * jj]     = *(const float4*)&Kg[(size_t)row * 512 + hb];
        kr[2 * jj + 1] = *(const float4*)&Kg[(size_t)row * 512 + hb + 8];
    }
    #pragma unroll
    for (int i = 0; i < 2; ++i)
        #pragma unroll
        for (int j = 0; j < 4; ++j) {
            const int lw = 32 * wm + 16 * i + g;
            const int f0 = 32 * wn + 8 * j + 2 * t;
            *(float2*)&sBD[lw * BDS + f0] = make_float2(accbd[i][j][0], accbd[i][j][1]);
            *(float2*)&sBD[(lw + 8) * BDS + f0] = make_float2(accbd[i][j][2], accbd[i][j][3]);
        }
    #pragma unroll
    for (int jj = 0; jj < 2; ++jj) {
        const int idx = tid + 256 * jj;
        const int row = 64 + (idx >> 3), kb = (idx >> 1) & 3, hh = idx & 1;
        *(uint4*)&sB[row * RS + kb * 8 + 4 * hh] = pack_quad(kr[2 * jj], kr[2 * jj + 1]);
    }
    __syncthreads();

    // ---- AC halves ----
    #pragma unroll 1
    for (int half = 0; half < 2; ++half) {
        float acc[2][4][4] = {};
        gemm_warp(sA, sB, acc, 32 * wm, 32 * wn, g, t);

        if (half == 0) {
            // gather K1 rows 128..191; epilogue hides the latency
            #pragma unroll
            for (int jj = 0; jj < 2; ++jj) {
                const int idx = tid + 256 * jj;
                const int row = 128 + (idx >> 3), kb = (idx >> 1) & 3, hh = idx & 1;
                const int hb = 16 * kb + 4 * hh;
                kr[2 * jj]     = *(const float4*)&Kg[(size_t)row * 512 + hb];
                kr[2 * jj + 1] = *(const float4*)&Kg[(size_t)row * 512 + hb + 8];
            }
        }

        // epilogue: add shifted BD, direct stores
        #pragma unroll
        for (int i = 0; i < 2; ++i)
            #pragma unroll
            for (int j = 0; j < 4; ++j) {
                const int c0 = 128 * half + 32 * wn + 8 * j + 2 * t;
                #pragma unroll
                for (int p = 0; p < 2; ++p) {
                    const int lw = 32 * wm + 16 * i + g + 8 * p;  // local row
                    const int wg = mh * 64 + lw;                  // global row
                    float v0 = acc[i][j][2 * p];
                    float v1 = acc[i][j][2 * p + 1];
                    const int f = c0 - wg;
                    if (f >= 0 && f < 128)          v0 += sBD[lw * BDS + f];
                    if (f + 1 >= 0 && f + 1 < 128)  v1 += sBD[lw * BDS + f + 1];
                    float* o = &OUT[(size_t)lw * Cc + c0];
                    o[0] = v0;
                    if (c0 + 1 < Cc) o[1] = v1;
                }
            }

        if (half == 0) {
            __syncthreads();                   // K0 fragment reads complete
            #pragma unroll
            for (int jj = 0; jj < 2; ++jj) {
                const int idx = tid + 256 * jj;
                const int row = (idx >> 3), kb = (idx >> 1) & 3, hh = idx & 1;
                *(uint4*)&sB[row * RS + kb * 8 + 4 * hh] = pack_quad(kr[2 * jj], kr[2 * jj + 1]);
            }
            // gather + store K1 rows 192..255 (row 255 zero)
            #pragma unroll
            for (int jj = 0; jj < 2; ++jj) {
                const int idx = tid + 256 * jj;
                const int row = 192 + (idx >> 3), kb = (idx >> 1) & 3, hh = idx & 1;
                const int hb = 16 * kb + 4 * hh;
                float4 z = make_float4(0.f, 0.f, 0.f, 0.f);
                kr[2 * jj]     = (row < Cc) ? *(const float4*)&Kg[(size_t)row * 512 + hb] : z;
                kr[2 * jj + 1] = (row < Cc) ? *(const float4*)&Kg[(size_t)row * 512 + hb + 8] : z;
            }
            #pragma unroll
            for (int jj = 0; jj < 2; ++jj) {
                const int idx = tid + 256 * jj;
                const int row = 64 + (idx >> 3), kb = (idx >> 1) & 3, hh = idx & 1;
                *(uint4*)&sB[row * RS + kb * 8 + 4 * hh] = pack_quad(kr[2 * jj], kr[2 * jj + 1]);
            }
            __syncthreads();
        }
    }
    (void)krow;
}

// ---------------------------------------------------------------------------
extern "C" void kernel_launch(void* const* d_in, const int* in_sizes, int n_in,
                              void* d_out, int out_size) {
    (void)in_sizes; (void)n_in; (void)out_size;
    const float* q  = (const float*)d_in[0];   // queries (4,32,128,8,64)
    const float* k  = (const float*)d_in[1];   // keys    (4,32,255,8,64)
    const float* pk = (const float*)d_in[2];   // pos_kernel (512,8,64)
    float* out = (float*)d_out;                // (4,8,32,128,255)

    compute_E_kernel<<<128, 1024>>>(pk);

    cudaFuncSetAttribute(txl_mma_kernel,
                         cudaFuncAttributeMaxDynamicSharedMemorySize, SMEM_BYTES);
    txl_mma_kernel<<<2 * 4 * Uu * Nn, 256, SMEM_BYTES>>>(q, k, out);
}